// round 10
// baseline (speedup 1.0000x reference)
#include <cuda_runtime.h>
#include <cuda_bf16.h>
#include <cuda_fp16.h>
#include <cuda_fp8.h>
#include <cstdint>

#define B_SZ 4096
#define D_SZ 1024
#define C_SZ 32
// bf16 rn scaled by sqrt(10*log2(e)); U/M sums divided by S2 later
#define RNSCALE 3.7982825500f
#define S2INV   (1.0f/14.4269504089f)
// fp8 rn scaled by 16; epilogue: exp(10 z) = 2^(acc * QC), QC = 10*log2(e)/256
#define QSCALE  16.0f
#define QC      0.05635527503472513f

#define BM 128
#define BN 128
#define BKQ 64            // fp8 elements per k-chunk
#define SKQ 80            // padded row stride in bytes (64 data + 16 pad)
#define STG (BM*SKQ)      // stage size: 10240 bytes
#define TTOT (B_SZ/BM)    // 32
#define NPAIR (TTOT*(TTOT+1)/2)  // 528

// small GEMM (U|M): RN^T [1024 x 4096] @ [soft | onehot] [4096 x 64]
#define KSPLIT 64
#define KCH (B_SZ/KSPLIT)   // 64
#define NSM 64

// ---------------- device scratch ----------------
__device__ __align__(128) __nv_bfloat16 g_rn[B_SZ * D_SZ];   // bf16, scale RNSCALE
__device__ __align__(128) uint8_t       g_rq[B_SZ * D_SZ];   // e4m3, scale QSCALE
__device__ float g_rowsumE[B_SZ];
__device__ float g_part[KSPLIT * 8 * 128 * NSM];   // split-k partials (16MB)
__device__ float g_Ssum[C_SZ];
__device__ int   g_hist[C_SZ];
__device__ int   g_labels[B_SZ];
__device__ float g_diagsum;
__device__ float g_accLog;
__device__ float g_sumU2;
__device__ float g_sumM2;

// ---------------- helpers ----------------
__device__ __forceinline__ float decode_pw(const void* p) {
    int v0 = ((const int*)p)[0];
    if (v0 > 0 && v0 < (1 << 26)) return (float)v0;
    float f = __int_as_float(v0);
    if (f > 0.0f && f < 1e8f) return f;
    return 0.0f;
}
__device__ __forceinline__ unsigned smem_u32(const void* p) {
    return (unsigned)__cvta_generic_to_shared(p);
}
__device__ __forceinline__ float ex2f(float x) {
    float y; asm("ex2.approx.f32 %0, %1;" : "=f"(y) : "f"(x)); return y;
}
__device__ __forceinline__ void cp16(unsigned dst, const void* src) {
    asm volatile("cp.async.cg.shared.global [%0], [%1], 16;" :: "r"(dst), "l"(src));
}
#define CP_COMMIT() asm volatile("cp.async.commit_group;" ::: "memory")
#define CP_WAIT(n)  asm volatile("cp.async.wait_group %0;" :: "n"(n) : "memory")
__device__ __forceinline__ void ldm_x4(unsigned addr, unsigned &r0, unsigned &r1, unsigned &r2, unsigned &r3) {
    asm volatile("ldmatrix.sync.aligned.m8n8.x4.shared.b16 {%0,%1,%2,%3}, [%4];"
                 : "=r"(r0), "=r"(r1), "=r"(r2), "=r"(r3) : "r"(addr));
}
__device__ __forceinline__ void ldm_x4_t(unsigned addr, unsigned &r0, unsigned &r1, unsigned &r2, unsigned &r3) {
    asm volatile("ldmatrix.sync.aligned.m8n8.x4.trans.shared.b16 {%0,%1,%2,%3}, [%4];"
                 : "=r"(r0), "=r"(r1), "=r"(r2), "=r"(r3) : "r"(addr));
}
__device__ __forceinline__ void ldm_x2_t(unsigned addr, unsigned &r0, unsigned &r1) {
    asm volatile("ldmatrix.sync.aligned.m8n8.x2.trans.shared.b16 {%0,%1}, [%2];"
                 : "=r"(r0), "=r"(r1) : "r"(addr));
}
__device__ __forceinline__ void mma16816(float &c0, float &c1, float &c2, float &c3,
                                         unsigned a0, unsigned a1, unsigned a2, unsigned a3,
                                         unsigned b0, unsigned b1) {
    asm volatile("mma.sync.aligned.m16n8k16.row.col.f32.bf16.bf16.f32 "
                 "{%0,%1,%2,%3},{%4,%5,%6,%7},{%8,%9},{%0,%1,%2,%3};"
                 : "+f"(c0), "+f"(c1), "+f"(c2), "+f"(c3)
                 : "r"(a0), "r"(a1), "r"(a2), "r"(a3), "r"(b0), "r"(b1));
}
// fp8 mma with f16 accumulator
__device__ __forceinline__ void mma16832h(unsigned &c0, unsigned &c1,
                                          unsigned a0, unsigned a1, unsigned a2, unsigned a3,
                                          unsigned b0, unsigned b1) {
    asm volatile("mma.sync.aligned.m16n8k32.row.col.f16.e4m3.e4m3.f16 "
                 "{%0,%1},{%2,%3,%4,%5},{%6,%7},{%0,%1};"
                 : "+r"(c0), "+r"(c1)
                 : "r"(a0), "r"(a1), "r"(a2), "r"(a3), "r"(b0), "r"(b1));
}
__device__ __forceinline__ uint16_t fp8pair(float lo, float hi) {
    uint16_t r;
    asm("cvt.rn.satfinite.e4m3x2.f32 %0, %1, %2;" : "=h"(r) : "f"(hi), "f"(lo));
    return r;
}

// ---------------- kernels ----------------
// fused zero + label decode
__global__ void k_init(const int* __restrict__ p) {
    __shared__ int is64;
    if (threadIdx.x == 0) {
        int any = 0;
        #pragma unroll
        for (int i = 1; i < 128; i += 2) any |= p[i];
        is64 = (any == 0) ? 1 : 0;
    }
    __syncthreads();
    int s64 = is64;
    int i = blockIdx.x * 256 + threadIdx.x;
    if (i < B_SZ) {
        g_rowsumE[i] = 0.f;
        g_labels[i] = s64 ? p[2 * i] : p[i];
    }
    if (i < C_SZ) { g_Ssum[i] = 0.f; g_hist[i] = 0; }
    if (i == 0) { g_diagsum = 0.f; g_accLog = 0.f; g_sumU2 = 0.f; g_sumM2 = 0.f; }
}

// one-pass normalize: bf16 (scale RNSCALE) + e4m3 (scale QSCALE)
__global__ __launch_bounds__(256) void k_norm(const float* __restrict__ reps, const float* __restrict__ soft) {
    int row = blockIdx.x;
    float4 v = ((const float4*)(reps + (size_t)row * D_SZ))[threadIdx.x];
    float ss = v.x * v.x + v.y * v.y + v.z * v.z + v.w * v.w;
    __shared__ float red[8];
    #pragma unroll
    for (int o = 16; o; o >>= 1) ss += __shfl_xor_sync(~0u, ss, o);
    if ((threadIdx.x & 31) == 0) red[threadIdx.x >> 5] = ss;
    __syncthreads();
    float sumsq = red[0] + red[1] + red[2] + red[3] + red[4] + red[5] + red[6] + red[7];
    float inv = 1.0f / fmaxf(sqrtf(sumsq), 1e-8f);
    float sc = inv * RNSCALE;
    __nv_bfloat162 p0 = __floats2bfloat162_rn(v.x * sc, v.y * sc);
    __nv_bfloat162 p1 = __floats2bfloat162_rn(v.z * sc, v.w * sc);
    uint2 pk; pk.x = *(uint32_t*)&p0; pk.y = *(uint32_t*)&p1;
    ((uint2*)(g_rn + (size_t)row * D_SZ))[threadIdx.x] = pk;
    float sq = inv * QSCALE;
    uint32_t q = (uint32_t)fp8pair(v.x * sq, v.y * sq)
               | ((uint32_t)fp8pair(v.z * sq, v.w * sq) << 16);
    ((uint32_t*)(g_rq + (size_t)row * D_SZ))[threadIdx.x] = q;
    if (threadIdx.x == 0) {
        atomicAdd(&g_diagsum, sumsq * inv * inv);
        atomicAdd(&g_hist[g_labels[row]], 1);
    }
    if (threadIdx.x < C_SZ) atomicAdd(&g_Ssum[threadIdx.x], soft[(size_t)row * C_SZ + threadIdx.x]);
}

// [U|M] = RN^T @ [soft | onehot] (scaled by RNSCALE), bf16 mma, split-k partials
__global__ __launch_bounds__(256) void k_small(const float* __restrict__ soft) {
    __shared__ __align__(16) __nv_bfloat16 rn_s[32][136];
    __shared__ __align__(16) __nv_bfloat16 sn_s[32][72];

    int mtile = blockIdx.x;   // 0..7
    int split = blockIdx.y;   // 0..KSPLIT-1
    int dbase = mtile * 128;
    int tid = threadIdx.x, lane = tid & 31, wid = tid >> 5;
    int wd = wid & 3, wn = wid >> 2;

    float acc[2][4][4];
    #pragma unroll
    for (int a = 0; a < 2; a++)
        #pragma unroll
        for (int b = 0; b < 4; b++)
            #pragma unroll
            for (int c = 0; c < 4; c++) acc[a][b][c] = 0.f;

    for (int ks = 0; ks < KCH / 32; ks++) {
        int i0 = split * KCH + ks * 32;
        #pragma unroll
        for (int j = 0; j < 2; j++) {
            int idx = tid + 256 * j;
            int row = idx >> 4, seg = idx & 15;
            *(uint4*)&rn_s[row][seg * 8] =
                *(const uint4*)(g_rn + (size_t)(i0 + row) * D_SZ + dbase + seg * 8);
        }
        {
            int i = tid >> 3, q = tid & 7;
            float4 sv = *(const float4*)(soft + (size_t)(i0 + i) * C_SZ + q * 4);
            __nv_bfloat162 p0 = __floats2bfloat162_rn(sv.x, sv.y);
            __nv_bfloat162 p1 = __floats2bfloat162_rn(sv.z, sv.w);
            uint2 pk; pk.x = *(uint32_t*)&p0; pk.y = *(uint32_t*)&p1;
            *(uint2*)&sn_s[i][q * 4] = pk;
            int lbl = g_labels[i0 + i];
            int n0 = q * 4;
            #pragma unroll
            for (int k = 0; k < 4; k++)
                sn_s[i][32 + n0 + k] = __float2bfloat16((lbl == n0 + k) ? 1.0f : 0.0f);
        }
        __syncthreads();

        unsigned a[2][2][4];
        #pragma unroll
        for (int mi = 0; mi < 2; mi++)
            #pragma unroll
            for (int kg = 0; kg < 2; kg++) {
                int krow = kg * 16 + (lane & 7) + ((lane >> 4) << 3);
                int mcol = wd * 32 + mi * 16 + ((lane >> 3) & 1) * 8;
                ldm_x4_t(smem_u32(&rn_s[krow][mcol]),
                         a[mi][kg][0], a[mi][kg][1], a[mi][kg][2], a[mi][kg][3]);
            }
        unsigned b[4][2][2];
        #pragma unroll
        for (int ni = 0; ni < 4; ni++)
            #pragma unroll
            for (int kg = 0; kg < 2; kg++) {
                int krow = kg * 16 + (lane & 15);
                ldm_x2_t(smem_u32(&sn_s[krow][wn * 32 + ni * 8]),
                         b[ni][kg][0], b[ni][kg][1]);
            }
        #pragma unroll
        for (int kg = 0; kg < 2; kg++)
            #pragma unroll
            for (int mi = 0; mi < 2; mi++)
                #pragma unroll
                for (int ni = 0; ni < 4; ni++)
                    mma16816(acc[mi][ni][0], acc[mi][ni][1], acc[mi][ni][2], acc[mi][ni][3],
                             a[mi][kg][0], a[mi][kg][1], a[mi][kg][2], a[mi][kg][3],
                             b[ni][kg][0], b[ni][kg][1]);
        __syncthreads();
    }

    #pragma unroll
    for (int mi = 0; mi < 2; mi++)
        #pragma unroll
        for (int ni = 0; ni < 4; ni++)
            #pragma unroll
            for (int r = 0; r < 4; r++) {
                int row = (lane >> 2) + (r >> 1) * 8;
                int col = (lane & 3) * 2 + (r & 1);
                int dl = wd * 32 + mi * 16 + row;
                int n  = wn * 32 + ni * 8 + col;
                g_part[((size_t)(split * 8 + mtile) * 128 + dl) * NSM + n] = acc[mi][ni][r];
            }
}

// main pass: fp8 e4m3 mma (f16 acc), triangular 128x128 tiles,
// 4 warps x 64x64 warp tiles, double-buffered cp.async, 4 CTA/SM (single wave)
__global__ __launch_bounds__(128, 4) void k_gemm_q() {
    __shared__ __align__(16) uint8_t sA[2][STG];
    __shared__ __align__(16) uint8_t sB[2][STG];
    __shared__ float rowbuf[BM];
    __shared__ float colbuf[BN];

    int idx = blockIdx.x;
    int I = 0;
    while (idx >= (TTOT - I)) { idx -= (TTOT - I); ++I; }
    int J = I + idx;
    bool diag = (I == J);

    int tid = threadIdx.x;
    int wid = tid >> 5, lane = tid & 31;
    int wm = wid & 1, wn = wid >> 1;       // 2x2 warps, 64x64 tile each

    rowbuf[tid] = 0.f; colbuf[tid] = 0.f;

    const uint8_t* pAr = g_rq + (size_t)(I * BM + tid) * D_SZ;   // one row per thread
    const uint8_t* pBr = g_rq + (size_t)(J * BN + tid) * D_SZ;
    const unsigned aBase = smem_u32(&sA[0][0]);
    const unsigned bBase = smem_u32(&sB[0][0]);
    unsigned dA = aBase + tid * SKQ;
    unsigned dB = bBase + tid * SKQ;

    const unsigned aoff0 = (unsigned)((wm * 64 + (lane & 15)) * SKQ + ((lane >> 4) << 4));
    const unsigned boff0 = (unsigned)((wn * 64 + ((lane >> 4) << 3) + (lane & 7)) * SKQ
                                      + (((lane >> 3) & 1) << 4));

    unsigned acc[4][8][2];
    #pragma unroll
    for (int a = 0; a < 4; a++)
        #pragma unroll
        for (int b = 0; b < 8; b++) { acc[a][b][0] = 0u; acc[a][b][1] = 0u; }

    const int KT = D_SZ / BKQ;   // 16
    // prologue: stage 0
    #pragma unroll
    for (int q = 0; q < 4; q++) {
        cp16(dA + q * 16, pAr + q * 16);
        cp16(dB + q * 16, pBr + q * 16);
    }
    CP_COMMIT();

    #pragma unroll 2
    for (int kt = 0; kt < KT; ++kt) {
        int buf = kt & 1;
        CP_WAIT(0);          // stage kt resident (this thread's copies)
        __syncthreads();     // visible to all; all warps done reading stage kt-1
        int nk = kt + 1;
        if (nk < KT) {
            unsigned dA2 = dA + (buf ^ 1) * STG;
            unsigned dB2 = dB + (buf ^ 1) * STG;
            const uint8_t* sa = pAr + nk * BKQ;
            const uint8_t* sb = pBr + nk * BKQ;
            #pragma unroll
            for (int q = 0; q < 4; q++) {
                cp16(dA2 + q * 16, sa + q * 16);
                cp16(dB2 + q * 16, sb + q * 16);
            }
        }
        CP_COMMIT();
        #pragma unroll
        for (int s = 0; s < 2; s++) {
            unsigned fa[4][4], fb[8][2];
            unsigned ab = aBase + buf * STG + aoff0 + s * 32;
            unsigned bb = bBase + buf * STG + boff0 + s * 32;
            #pragma unroll
            for (int mi = 0; mi < 4; mi++)
                ldm_x4(ab + mi * 16 * SKQ, fa[mi][0], fa[mi][1], fa[mi][2], fa[mi][3]);
            #pragma unroll
            for (int nj = 0; nj < 4; nj++)
                ldm_x4(bb + nj * 16 * SKQ, fb[2 * nj][0], fb[2 * nj][1],
                                           fb[2 * nj + 1][0], fb[2 * nj + 1][1]);
            #pragma unroll
            for (int mi = 0; mi < 4; mi++)
                #pragma unroll
                for (int ni = 0; ni < 8; ni++)
                    mma16832h(acc[mi][ni][0], acc[mi][ni][1],
                              fa[mi][0], fa[mi][1], fa[mi][2], fa[mi][3],
                              fb[ni][0], fb[ni][1]);
        }
    }

    // epilogue: e = 2^(acc*QC); row sums (I) and col sums (J)
    int g = lane >> 2, t = lane & 3;
    int rbase = wm * 64, cbase = wn * 64;
    float colp[8][2];
    #pragma unroll
    for (int ni = 0; ni < 8; ni++) { colp[ni][0] = 0.f; colp[ni][1] = 0.f; }

    #pragma unroll
    for (int mi = 0; mi < 4; mi++) {
        float r0 = 0.f, r1 = 0.f;
        #pragma unroll
        for (int ni = 0; ni < 8; ni++) {
            float2 f0 = __half22float2(*(__half2*)&acc[mi][ni][0]);   // row g,   cols t2,t2+1
            float2 f1 = __half22float2(*(__half2*)&acc[mi][ni][1]);   // row g+8, cols t2,t2+1
            float e0 = ex2f(f0.x * QC);
            float e1 = ex2f(f0.y * QC);
            float e2 = ex2f(f1.x * QC);
            float e3 = ex2f(f1.y * QC);
            if (diag) {
                int r = rbase + mi * 16 + g, c = cbase + ni * 8 + t * 2;
                if (r == c)     e0 = 0.f;
                if (r == c + 1) e1 = 0.f;
                if (r + 8 == c)     e2 = 0.f;
                if (r + 8 == c + 1) e3 = 0.f;
            }
            r0 += e0 + e1; r1 += e2 + e3;
            colp[ni][0] += e0 + e2; colp[ni][1] += e1 + e3;
        }
        r0 += __shfl_xor_sync(~0u, r0, 1); r0 += __shfl_xor_sync(~0u, r0, 2);
        r1 += __shfl_xor_sync(~0u, r1, 1); r1 += __shfl_xor_sync(~0u, r1, 2);
        if (t == 0) {
            atomicAdd(&rowbuf[rbase + mi * 16 + g],     r0);
            atomicAdd(&rowbuf[rbase + mi * 16 + g + 8], r1);
        }
    }
    if (!diag) {
        #pragma unroll
        for (int ni = 0; ni < 8; ni++) {
            #pragma unroll
            for (int p = 0; p < 2; p++) {
                float v = colp[ni][p];
                v += __shfl_xor_sync(~0u, v, 4);
                v += __shfl_xor_sync(~0u, v, 8);
                v += __shfl_xor_sync(~0u, v, 16);
                if (lane < 4) atomicAdd(&colbuf[cbase + ni * 8 + lane * 2 + p], v);
            }
        }
    }
    __syncthreads();
    atomicAdd(&g_rowsumE[I * BM + tid], rowbuf[tid]);
    if (!diag) atomicAdd(&g_rowsumE[J * BN + tid], colbuf[tid]);
}

// fused: blocks [0,256) reduce split-k partials; blocks [256,272) row terms
__global__ void k_tail(const float* __restrict__ soft, const void* pwp) {
    if (blockIdx.x < 256) {
        int idx = blockIdx.x * 256 + threadIdx.x;
        float su = 0.f, sm = 0.f;
        {
            int d = idx >> 6, n = idx & 63;
            int mt = d >> 7, dl = d & 127;
            float s = 0.f;
            #pragma unroll
            for (int sp = 0; sp < KSPLIT; sp++)
                s += g_part[((size_t)(sp * 8 + mt) * 128 + dl) * NSM + n];
            if (n < C_SZ) su = s * s; else sm = s * s;
        }
        #pragma unroll
        for (int o = 16; o; o >>= 1) { su += __shfl_xor_sync(~0u, su, o); sm += __shfl_xor_sync(~0u, sm, o); }
        __shared__ float rs[8], rm[8];
        if ((threadIdx.x & 31) == 0) { rs[threadIdx.x >> 5] = su; rm[threadIdx.x >> 5] = sm; }
        __syncthreads();
        if (threadIdx.x < 8) {
            float a = rs[threadIdx.x], b = rm[threadIdx.x];
            #pragma unroll
            for (int o = 4; o; o >>= 1) { a += __shfl_xor_sync(0xff, a, o); b += __shfl_xor_sync(0xff, b, o); }
            if (threadIdx.x == 0) { atomicAdd(&g_sumU2, a); atomicAdd(&g_sumM2, b); }
        }
    } else {
        float pw = decode_pw(pwp);
        int i = (blockIdx.x - 256) * 256 + threadIdx.x;
        float term = 0.f;
        {
            int lbl = g_labels[i];
            float wsum = (float)(g_hist[lbl] - 1);
            const float* s = soft + (size_t)i * C_SZ;
            float d = 0.f;
            #pragma unroll
            for (int c = 0; c < C_SZ; c++) d += s[c] * g_Ssum[c];
            wsum += pw * d;
            term = wsum * logf(g_rowsumE[i]);
        }
        #pragma unroll
        for (int o = 16; o; o >>= 1) term += __shfl_xor_sync(~0u, term, o);
        __shared__ float red[8];
        if ((threadIdx.x & 31) == 0) red[threadIdx.x >> 5] = term;
        __syncthreads();
        if (threadIdx.x < 8) {
            float v = red[threadIdx.x];
            #pragma unroll
            for (int o = 4; o; o >>= 1) v += __shfl_xor_sync(0xff, v, o);
            if (threadIdx.x == 0) atomicAdd(&g_accLog, v);
        }
    }
}

__global__ void k_out(float* out, const void* pwp) {
    float pw = decode_pw(pwp);
    float P  = (g_sumM2 * S2INV - g_diagsum) * 10.0f;
    float SZ = (g_sumU2 * S2INV) * 10.0f;
    out[0] = (g_accLog - P - pw * SZ) / (float)B_SZ;
}

// ---------------- launch ----------------
extern "C" void kernel_launch(void* const* d_in, const int* in_sizes, int n_in,
                              void* d_out, int out_size) {
    const float* reps = (const float*)d_in[0];
    const float* soft = (const float*)d_in[1];
    const int*   lblp = (const int*)d_in[2];
    const void*  pwp  = d_in[3];
    float* out = (float*)d_out;
    (void)in_sizes; (void)n_in; (void)out_size;

    k_init<<<16, 256>>>(lblp);
    k_norm<<<B_SZ, 256>>>(reps, soft);
    k_small<<<dim3(8, KSPLIT), 256>>>(soft);
    k_gemm_q<<<NPAIR, 128>>>();
    k_tail<<<272, 256>>>(soft, pwp);
    k_out<<<1, 1>>>(out, pwp);
}

// round 12
// speedup vs baseline: 1.2416x; 1.2416x over previous
#include <cuda_runtime.h>
#include <cuda_bf16.h>
#include <cuda_fp16.h>
#include <cuda_fp8.h>
#include <cstdint>

#define B_SZ 4096
#define D_SZ 1024
#define C_SZ 32
// bf16 rn scaled by sqrt(10*log2(e)); U/M sums divided by S2 later
#define RNSCALE 3.7982825500f
#define S2INV   (1.0f/14.4269504089f)
// fp8 rn scaled by 16; epilogue: exp(10 z) = 2^(acc * QC), QC = 10*log2(e)/256
#define QSCALE  16.0f
#define QC      0.05635527503472513f

#define BM 128
#define BN 128
#define TTOT (B_SZ/BM)    // 32
#define NPAIR (TTOT*(TTOT+1)/2)  // 528
#define KT_G 16           // k-chunks of 64 fp8
#define CHUNK 8192        // one (tile, kt) chunk: 128 rows x 64B, swizzled

// dynamic smem layout for k_gemm_q
#define SM_AB(s)  ((s) * 16384)          // A at +0 (8KB), B at +8192
#define SM_MB     65536                   // 4 mbarriers
#define SM_ROW    65600
#define SM_COL    66112
#define SM_TOT    66624

// small GEMM (U|M): RN^T [1024 x 4096] @ [soft | onehot] [4096 x 64]
#define KSPLIT 64
#define KCH (B_SZ/KSPLIT)   // 64
#define NSM 64

// ---------------- device scratch ----------------
__device__ __align__(128) __nv_bfloat16 g_rn[B_SZ * D_SZ];   // bf16, scale RNSCALE
__device__ __align__(128) uint8_t       g_rq[B_SZ * D_SZ];   // e4m3 in (tile,kt)-chunk swizzled layout
__device__ float g_rowsumE[B_SZ];
__device__ float g_part[KSPLIT * 8 * 128 * NSM];   // split-k partials
__device__ float g_Ssum[C_SZ];
__device__ int   g_hist[C_SZ];
__device__ int   g_labels[B_SZ];
__device__ float g_diagsum;
__device__ float g_accLog;
__device__ float g_sumU2;
__device__ float g_sumM2;

// ---------------- helpers ----------------
__device__ __forceinline__ float decode_pw(const void* p) {
    int v0 = ((const int*)p)[0];
    if (v0 > 0 && v0 < (1 << 26)) return (float)v0;
    float f = __int_as_float(v0);
    if (f > 0.0f && f < 1e8f) return f;
    return 0.0f;
}
__device__ __forceinline__ unsigned smem_u32(const void* p) {
    return (unsigned)__cvta_generic_to_shared(p);
}
__device__ __forceinline__ float ex2f(float x) {
    float y; asm("ex2.approx.f32 %0, %1;" : "=f"(y) : "f"(x)); return y;
}
__device__ __forceinline__ void mbar_init(uint32_t a, uint32_t cnt) {
    asm volatile("mbarrier.init.shared.b64 [%0], %1;" :: "r"(a), "r"(cnt) : "memory");
}
__device__ __forceinline__ void mbar_expect_tx(uint32_t a, uint32_t bytes) {
    asm volatile("mbarrier.arrive.expect_tx.shared.b64 _, [%0], %1;" :: "r"(a), "r"(bytes) : "memory");
}
__device__ __forceinline__ void mbar_wait(uint32_t a, uint32_t parity) {
    asm volatile(
        "{\n\t.reg .pred P;\n\t"
        "WL_%=:\n\t"
        "mbarrier.try_wait.parity.acquire.cta.shared::cta.b64 P, [%0], %1, 0x989680;\n\t"
        "@P bra.uni WD_%=;\n\t"
        "bra.uni WL_%=;\n\t"
        "WD_%=:\n\t}"
        :: "r"(a), "r"(parity) : "memory");
}
__device__ __forceinline__ void bulk_g2s(uint32_t dst, const void* src, uint32_t bytes, uint32_t mbar) {
    asm volatile("cp.async.bulk.shared::cluster.global.mbarrier::complete_tx::bytes [%0], [%1], %2, [%3];"
                 :: "r"(dst), "l"(src), "r"(bytes), "r"(mbar) : "memory");
}
__device__ __forceinline__ void ldm_x4(unsigned addr, unsigned &r0, unsigned &r1, unsigned &r2, unsigned &r3) {
    asm volatile("ldmatrix.sync.aligned.m8n8.x4.shared.b16 {%0,%1,%2,%3}, [%4];"
                 : "=r"(r0), "=r"(r1), "=r"(r2), "=r"(r3) : "r"(addr));
}
__device__ __forceinline__ void ldm_x4_t(unsigned addr, unsigned &r0, unsigned &r1, unsigned &r2, unsigned &r3) {
    asm volatile("ldmatrix.sync.aligned.m8n8.x4.trans.shared.b16 {%0,%1,%2,%3}, [%4];"
                 : "=r"(r0), "=r"(r1), "=r"(r2), "=r"(r3) : "r"(addr));
}
__device__ __forceinline__ void ldm_x2_t(unsigned addr, unsigned &r0, unsigned &r1) {
    asm volatile("ldmatrix.sync.aligned.m8n8.x2.trans.shared.b16 {%0,%1}, [%2];"
                 : "=r"(r0), "=r"(r1) : "r"(addr));
}
__device__ __forceinline__ void mma16816(float &c0, float &c1, float &c2, float &c3,
                                         unsigned a0, unsigned a1, unsigned a2, unsigned a3,
                                         unsigned b0, unsigned b1) {
    asm volatile("mma.sync.aligned.m16n8k16.row.col.f32.bf16.bf16.f32 "
                 "{%0,%1,%2,%3},{%4,%5,%6,%7},{%8,%9},{%0,%1,%2,%3};"
                 : "+f"(c0), "+f"(c1), "+f"(c2), "+f"(c3)
                 : "r"(a0), "r"(a1), "r"(a2), "r"(a3), "r"(b0), "r"(b1));
}
// fp8 mma with f16 accumulator
__device__ __forceinline__ void mma16832h(unsigned &c0, unsigned &c1,
                                          unsigned a0, unsigned a1, unsigned a2, unsigned a3,
                                          unsigned b0, unsigned b1) {
    asm volatile("mma.sync.aligned.m16n8k32.row.col.f16.e4m3.e4m3.f16 "
                 "{%0,%1},{%2,%3,%4,%5},{%6,%7},{%0,%1};"
                 : "+r"(c0), "+r"(c1)
                 : "r"(a0), "r"(a1), "r"(a2), "r"(a3), "r"(b0), "r"(b1));
}
__device__ __forceinline__ uint16_t fp8pair(float lo, float hi) {
    uint16_t r;
    asm("cvt.rn.satfinite.e4m3x2.f32 %0, %1, %2;" : "=h"(r) : "f"(hi), "f"(lo));
    return r;
}

// ---------------- kernels ----------------
// fused zero + label decode
__global__ void k_init(const int* __restrict__ p) {
    __shared__ int is64;
    if (threadIdx.x == 0) {
        int any = 0;
        #pragma unroll
        for (int i = 1; i < 128; i += 2) any |= p[i];
        is64 = (any == 0) ? 1 : 0;
    }
    __syncthreads();
    int s64 = is64;
    int i = blockIdx.x * 256 + threadIdx.x;
    if (i < B_SZ) {
        g_rowsumE[i] = 0.f;
        g_labels[i] = s64 ? p[2 * i] : p[i];
    }
    if (i < C_SZ) { g_Ssum[i] = 0.f; g_hist[i] = 0; }
    if (i == 0) { g_diagsum = 0.f; g_accLog = 0.f; g_sumU2 = 0.f; g_sumM2 = 0.f; }
}

// one-pass normalize: bf16 row-major + e4m3 in (tile,kt)-chunk swizzled layout
__global__ __launch_bounds__(256) void k_norm(const float* __restrict__ reps, const float* __restrict__ soft) {
    int row = blockIdx.x;
    float4 v = ((const float4*)(reps + (size_t)row * D_SZ))[threadIdx.x];
    float ss = v.x * v.x + v.y * v.y + v.z * v.z + v.w * v.w;
    __shared__ float red[8];
    #pragma unroll
    for (int o = 16; o; o >>= 1) ss += __shfl_xor_sync(~0u, ss, o);
    if ((threadIdx.x & 31) == 0) red[threadIdx.x >> 5] = ss;
    __syncthreads();
    float sumsq = red[0] + red[1] + red[2] + red[3] + red[4] + red[5] + red[6] + red[7];
    float inv = 1.0f / fmaxf(sqrtf(sumsq), 1e-8f);
    float sc = inv * RNSCALE;
    __nv_bfloat162 p0 = __floats2bfloat162_rn(v.x * sc, v.y * sc);
    __nv_bfloat162 p1 = __floats2bfloat162_rn(v.z * sc, v.w * sc);
    uint2 pk; pk.x = *(uint32_t*)&p0; pk.y = *(uint32_t*)&p1;
    ((uint2*)(g_rn + (size_t)row * D_SZ))[threadIdx.x] = pk;
    float sq = inv * QSCALE;
    uint32_t q = (uint32_t)fp8pair(v.x * sq, v.y * sq)
               | ((uint32_t)fp8pair(v.z * sq, v.w * sq) << 16);
    {   // chunked + swizzled fp8 store
        int tile = row >> 7, lrow = row & 127;
        int ktc = threadIdx.x >> 4;            // col/64
        unsigned cb = (threadIdx.x & 15) * 4;  // byte within 64B chunk row
        unsigned off = ((unsigned)lrow << 6) | cb;
        off ^= ((unsigned)(lrow >> 1) & 7u) << 4;
        *(uint32_t*)(g_rq + ((size_t)(tile * KT_G + ktc) << 13) + off) = q;
    }
    if (threadIdx.x == 0) {
        atomicAdd(&g_diagsum, sumsq * inv * inv);
        atomicAdd(&g_hist[g_labels[row]], 1);
    }
    if (threadIdx.x < C_SZ) atomicAdd(&g_Ssum[threadIdx.x], soft[(size_t)row * C_SZ + threadIdx.x]);
}

// [U|M] = RN^T @ [soft | onehot] (scaled by RNSCALE), bf16 mma, split-k partials
__global__ __launch_bounds__(256) void k_small(const float* __restrict__ soft) {
    __shared__ __align__(16) __nv_bfloat16 rn_s[32][136];
    __shared__ __align__(16) __nv_bfloat16 sn_s[32][72];

    int mtile = blockIdx.x;   // 0..7
    int split = blockIdx.y;   // 0..KSPLIT-1
    int dbase = mtile * 128;
    int tid = threadIdx.x, lane = tid & 31, wid = tid >> 5;
    int wd = wid & 3, wn = wid >> 2;

    float acc[2][4][4];
    #pragma unroll
    for (int a = 0; a < 2; a++)
        #pragma unroll
        for (int b = 0; b < 4; b++)
            #pragma unroll
            for (int c = 0; c < 4; c++) acc[a][b][c] = 0.f;

    for (int ks = 0; ks < KCH / 32; ks++) {
        int i0 = split * KCH + ks * 32;
        #pragma unroll
        for (int j = 0; j < 2; j++) {
            int idx = tid + 256 * j;
            int row = idx >> 4, seg = idx & 15;
            *(uint4*)&rn_s[row][seg * 8] =
                *(const uint4*)(g_rn + (size_t)(i0 + row) * D_SZ + dbase + seg * 8);
        }
        {
            int i = tid >> 3, q = tid & 7;
            float4 sv = *(const float4*)(soft + (size_t)(i0 + i) * C_SZ + q * 4);
            __nv_bfloat162 p0 = __floats2bfloat162_rn(sv.x, sv.y);
            __nv_bfloat162 p1 = __floats2bfloat162_rn(sv.z, sv.w);
            uint2 pk; pk.x = *(uint32_t*)&p0; pk.y = *(uint32_t*)&p1;
            *(uint2*)&sn_s[i][q * 4] = pk;
            int lbl = g_labels[i0 + i];
            int n0 = q * 4;
            #pragma unroll
            for (int k = 0; k < 4; k++)
                sn_s[i][32 + n0 + k] = __float2bfloat16((lbl == n0 + k) ? 1.0f : 0.0f);
        }
        __syncthreads();

        unsigned a[2][2][4];
        #pragma unroll
        for (int mi = 0; mi < 2; mi++)
            #pragma unroll
            for (int kg = 0; kg < 2; kg++) {
                int krow = kg * 16 + (lane & 7) + ((lane >> 4) << 3);
                int mcol = wd * 32 + mi * 16 + ((lane >> 3) & 1) * 8;
                ldm_x4_t(smem_u32(&rn_s[krow][mcol]),
                         a[mi][kg][0], a[mi][kg][1], a[mi][kg][2], a[mi][kg][3]);
            }
        unsigned b[4][2][2];
        #pragma unroll
        for (int ni = 0; ni < 4; ni++)
            #pragma unroll
            for (int kg = 0; kg < 2; kg++) {
                int krow = kg * 16 + (lane & 15);
                ldm_x2_t(smem_u32(&sn_s[krow][wn * 32 + ni * 8]),
                         b[ni][kg][0], b[ni][kg][1]);
            }
        #pragma unroll
        for (int kg = 0; kg < 2; kg++)
            #pragma unroll
            for (int mi = 0; mi < 2; mi++)
                #pragma unroll
                for (int ni = 0; ni < 4; ni++)
                    mma16816(acc[mi][ni][0], acc[mi][ni][1], acc[mi][ni][2], acc[mi][ni][3],
                             a[mi][kg][0], a[mi][kg][1], a[mi][kg][2], a[mi][kg][3],
                             b[ni][kg][0], b[ni][kg][1]);
        __syncthreads();
    }

    #pragma unroll
    for (int mi = 0; mi < 2; mi++)
        #pragma unroll
        for (int ni = 0; ni < 4; ni++)
            #pragma unroll
            for (int r = 0; r < 4; r++) {
                int row = (lane >> 2) + (r >> 1) * 8;
                int col = (lane & 3) * 2 + (r & 1);
                int dl = wd * 32 + mi * 16 + row;
                int n  = wn * 32 + ni * 8 + col;
                g_part[((size_t)(split * 8 + mtile) * 128 + dl) * NSM + n] = acc[mi][ni][r];
            }
}

// swizzled smem address within a chunk: (row, 16B-quad qi)
__device__ __forceinline__ unsigned swz_addr(unsigned base, int row, int qi) {
    unsigned off = ((unsigned)row << 6) + ((unsigned)qi << 4);
    off ^= ((unsigned)(row >> 1) & 7u) << 4;
    return base + off;
}

// main pass: fp8 e4m3 mma (f16 acc), triangular 128x128 tiles,
// cp.async.bulk 8KB chunk copies + mbarrier ring (4 stages), 8 warps x 64x32 tiles, 2 CTA/SM
__global__ __launch_bounds__(256, 2) void k_gemm_q() {
    extern __shared__ __align__(128) uint8_t smem[];
    const unsigned sb = smem_u32(smem);
    float* rowbuf = (float*)(smem + SM_ROW);
    float* colbuf = (float*)(smem + SM_COL);

    int idx = blockIdx.x;
    int I = 0;
    while (idx >= (TTOT - I)) { idx -= (TTOT - I); ++I; }
    int J = I + idx;
    bool diag = (I == J);

    int tid = threadIdx.x;
    int wid = tid >> 5, lane = tid & 31;
    int wm = wid & 1, wn = wid >> 1;       // 2x4 warps, 64x32 warp tiles

    if (tid < BM) { rowbuf[tid] = 0.f; colbuf[tid] = 0.f; }

    const uint8_t* gA = g_rq + ((size_t)I * KT_G << 13);
    const uint8_t* gB = g_rq + ((size_t)J * KT_G << 13);

    if (tid == 0) {
        #pragma unroll
        for (int s = 0; s < 4; s++) mbar_init(sb + SM_MB + s * 8, 1);
    }
    __syncthreads();
    if (tid == 0) {
        #pragma unroll
        for (int p = 0; p < 3; p++) {
            unsigned mb = sb + SM_MB + p * 8;
            mbar_expect_tx(mb, 2 * CHUNK);
            bulk_g2s(sb + SM_AB(p),         gA + p * CHUNK, CHUNK, mb);
            bulk_g2s(sb + SM_AB(p) + CHUNK, gB + p * CHUNK, CHUNK, mb);
        }
    }

    unsigned acc[4][4][2];
    #pragma unroll
    for (int a = 0; a < 4; a++)
        #pragma unroll
        for (int b = 0; b < 4; b++) { acc[a][b][0] = 0u; acc[a][b][1] = 0u; }

    const int arow0 = wm * 64 + (lane & 15);
    const int aq0   = lane >> 4;
    const int brow0 = wn * 32 + ((lane >> 4) << 3) + (lane & 7);
    const int bq0   = (lane >> 3) & 1;

    for (int kt = 0; kt < KT_G; ++kt) {
        if (kt) __syncthreads();            // all warps done reading stage (kt-1)&3
        if (tid == 0) {
            int nk = kt + 3;
            if (nk < KT_G) {
                int nb = nk & 3;
                unsigned mb = sb + SM_MB + nb * 8;
                mbar_expect_tx(mb, 2 * CHUNK);
                bulk_g2s(sb + SM_AB(nb),         gA + nk * CHUNK, CHUNK, mb);
                bulk_g2s(sb + SM_AB(nb) + CHUNK, gB + nk * CHUNK, CHUNK, mb);
            }
        }
        int st = kt & 3;
        mbar_wait(sb + SM_MB + st * 8, (kt >> 2) & 1);
        unsigned aBase = sb + SM_AB(st);
        unsigned bBase = aBase + CHUNK;
        #pragma unroll
        for (int s = 0; s < 2; s++) {
            unsigned fa[4][4], fb[4][2];
            #pragma unroll
            for (int mi = 0; mi < 4; mi++)
                ldm_x4(swz_addr(aBase, arow0 + mi * 16, s * 2 + aq0),
                       fa[mi][0], fa[mi][1], fa[mi][2], fa[mi][3]);
            #pragma unroll
            for (int nj = 0; nj < 2; nj++)
                ldm_x4(swz_addr(bBase, brow0 + nj * 16, s * 2 + bq0),
                       fb[2 * nj][0], fb[2 * nj][1], fb[2 * nj + 1][0], fb[2 * nj + 1][1]);
            #pragma unroll
            for (int mi = 0; mi < 4; mi++)
                #pragma unroll
                for (int ni = 0; ni < 4; ni++)
                    mma16832h(acc[mi][ni][0], acc[mi][ni][1],
                              fa[mi][0], fa[mi][1], fa[mi][2], fa[mi][3],
                              fb[ni][0], fb[ni][1]);
        }
    }

    // epilogue: e = 2^(acc*QC); row sums (I) and col sums (J)
    int g = lane >> 2, t = lane & 3;
    int rbase = wm * 64, cbase = wn * 32;
    float colp[4][2];
    #pragma unroll
    for (int ni = 0; ni < 4; ni++) { colp[ni][0] = 0.f; colp[ni][1] = 0.f; }

    #pragma unroll
    for (int mi = 0; mi < 4; mi++) {
        float r0 = 0.f, r1 = 0.f;
        #pragma unroll
        for (int ni = 0; ni < 4; ni++) {
            float2 f0 = __half22float2(*(__half2*)&acc[mi][ni][0]);   // row g,   cols 2t,2t+1
            float2 f1 = __half22float2(*(__half2*)&acc[mi][ni][1]);   // row g+8, cols 2t,2t+1
            float e0 = ex2f(f0.x * QC);
            float e1 = ex2f(f0.y * QC);
            float e2 = ex2f(f1.x * QC);
            float e3 = ex2f(f1.y * QC);
            if (diag) {
                int r = rbase + mi * 16 + g, c = cbase + ni * 8 + t * 2;
                if (r == c)     e0 = 0.f;
                if (r == c + 1) e1 = 0.f;
                if (r + 8 == c)     e2 = 0.f;
                if (r + 8 == c + 1) e3 = 0.f;
            }
            r0 += e0 + e1; r1 += e2 + e3;
            colp[ni][0] += e0 + e2; colp[ni][1] += e1 + e3;
        }
        r0 += __shfl_xor_sync(~0u, r0, 1); r0 += __shfl_xor_sync(~0u, r0, 2);
        r1 += __shfl_xor_sync(~0u, r1, 1); r1 += __shfl_xor_sync(~0u, r1, 2);
        if (t == 0) {
            atomicAdd(&rowbuf[rbase + mi * 16 + g],     r0);
            atomicAdd(&rowbuf[rbase + mi * 16 + g + 8], r1);
        }
    }
    if (!diag) {
        #pragma unroll
        for (int ni = 0; ni < 4; ni++) {
            #pragma unroll
            for (int p = 0; p < 2; p++) {
                float v = colp[ni][p];
                v += __shfl_xor_sync(~0u, v, 4);
                v += __shfl_xor_sync(~0u, v, 8);
                v += __shfl_xor_sync(~0u, v, 16);
                if (lane < 4) atomicAdd(&colbuf[cbase + ni * 8 + lane * 2 + p], v);
            }
        }
    }
    __syncthreads();
    if (tid < BM) {
        atomicAdd(&g_rowsumE[I * BM + tid], rowbuf[tid]);
        if (!diag) atomicAdd(&g_rowsumE[J * BN + tid], colbuf[tid]);
    }
}

// fused: blocks [0,256) reduce split-k partials; blocks [256,272) row terms
__global__ void k_tail(const float* __restrict__ soft, const void* pwp) {
    if (blockIdx.x < 256) {
        int idx = blockIdx.x * 256 + threadIdx.x;
        float su = 0.f, sm = 0.f;
        {
            int d = idx >> 6, n = idx & 63;
            int mt = d >> 7, dl = d & 127;
            float s = 0.f;
            #pragma unroll
            for (int sp = 0; sp < KSPLIT; sp++)
                s += g_part[((size_t)(sp * 8 + mt) * 128 + dl) * NSM + n];
            if (n < C_SZ) su = s * s; else sm = s * s;
        }
        #pragma unroll
        for (int o = 16; o; o >>= 1) { su += __shfl_xor_sync(~0u, su, o); sm += __shfl_xor_sync(~0u, sm, o); }
        __shared__ float rs[8], rm[8];
        if ((threadIdx.x & 31) == 0) { rs[threadIdx.x >> 5] = su; rm[threadIdx.x >> 5] = sm; }
        __syncthreads();
        if (threadIdx.x < 8) {
            float a = rs[threadIdx.x], b = rm[threadIdx.x];
            #pragma unroll
            for (int o = 4; o; o >>= 1) { a += __shfl_xor_sync(0xff, a, o); b += __shfl_xor_sync(0xff, b, o); }
            if (threadIdx.x == 0) { atomicAdd(&g_sumU2, a); atomicAdd(&g_sumM2, b); }
        }
    } else {
        float pw = decode_pw(pwp);
        int i = (blockIdx.x - 256) * 256 + threadIdx.x;
        float term = 0.f;
        {
            int lbl = g_labels[i];
            float wsum = (float)(g_hist[lbl] - 1);
            const float* s = soft + (size_t)i * C_SZ;
            float d = 0.f;
            #pragma unroll
            for (int c = 0; c < C_SZ; c++) d += s[c] * g_Ssum[c];
            wsum += pw * d;
            term = wsum * logf(g_rowsumE[i]);
        }
        #pragma unroll
        for (int o = 16; o; o >>= 1) term += __shfl_xor_sync(~0u, term, o);
        __shared__ float red[8];
        if ((threadIdx.x & 31) == 0) red[threadIdx.x >> 5] = term;
        __syncthreads();
        if (threadIdx.x < 8) {
            float v = red[threadIdx.x];
            #pragma unroll
            for (int o = 4; o; o >>= 1) v += __shfl_xor_sync(0xff, v, o);
            if (threadIdx.x == 0) atomicAdd(&g_accLog, v);
        }
    }
}

__global__ void k_out(float* out, const void* pwp) {
    float pw = decode_pw(pwp);
    float P  = (g_sumM2 * S2INV - g_diagsum) * 10.0f;
    float SZ = (g_sumU2 * S2INV) * 10.0f;
    out[0] = (g_accLog - P - pw * SZ) / (float)B_SZ;
}

// ---------------- launch ----------------
extern "C" void kernel_launch(void* const* d_in, const int* in_sizes, int n_in,
                              void* d_out, int out_size) {
    const float* reps = (const float*)d_in[0];
    const float* soft = (const float*)d_in[1];
    const int*   lblp = (const int*)d_in[2];
    const void*  pwp  = d_in[3];
    float* out = (float*)d_out;
    (void)in_sizes; (void)n_in; (void)out_size;

    cudaFuncSetAttribute(k_gemm_q, cudaFuncAttributeMaxDynamicSharedMemorySize, SM_TOT);

    k_init<<<16, 256>>>(lblp);
    k_norm<<<B_SZ, 256>>>(reps, soft);
    k_small<<<dim3(8, KSPLIT), 256>>>(soft);
    k_gemm_q<<<NPAIR, 256, SM_TOT>>>();
    k_tail<<<272, 256>>>(soft, pwp);
    k_out<<<1, 1>>>(out, pwp);
}

// round 15
// speedup vs baseline: 1.2729x; 1.0252x over previous
#include <cuda_runtime.h>
#include <cuda_bf16.h>
#include <cuda_fp16.h>
#include <cuda_fp8.h>
#include <cstdint>

#define B_SZ 4096
#define D_SZ 1024
#define C_SZ 32
// bf16 rn scaled by sqrt(10*log2(e)); U/M sums divided by S2 later
#define RNSCALE 3.7982825500f
#define S2INV   (1.0f/14.4269504089f)
// fp8 rn scaled by 16; epilogue: exp(10 z) = 2^(acc * QC), QC = 10*log2(e)/256
#define QSCALE  16.0f
#define QC      0.05635527503472513f

#define BM 128
#define BN 128
#define TTOT (B_SZ/BM)    // 32
#define NPAIR (TTOT*(TTOT+1)/2)  // 528
#define KT_G 8            // k-chunks of 128 fp8
#define CHUNK 16384       // one (tile, kt) chunk: 128 rows x 128B, SW128 swizzled

// dynamic smem layout for k_gemm_q (3-stage ring)
#define SM_AB(s)  ((s) * 32768)          // A at +0 (16KB), B at +16384
#define SM_MB     98304                   // 3 mbarriers
#define SM_ROW    98368
#define SM_COL    98880
#define SM_TOT    99392

// small GEMM (U|M): RN^T [1024 x 4096] @ [soft | onehot] [4096 x 64]
#define KSPLIT 64
#define KCH (B_SZ/KSPLIT)   // 64
#define NSM 64

// ---------------- device scratch ----------------
__device__ __align__(128) __nv_bfloat16 g_rn[B_SZ * D_SZ];   // bf16, scale RNSCALE
__device__ __align__(128) uint8_t       g_rq[B_SZ * D_SZ];   // e4m3, (tile,kt)-chunk SW128 layout
__device__ float g_rowsumE[B_SZ];
__device__ float g_part[KSPLIT * 8 * 128 * NSM];   // split-k partials
__device__ float g_Ssum[C_SZ];
__device__ int   g_hist[C_SZ];
__device__ int   g_labels[B_SZ];
__device__ float g_diagsum;
__device__ float g_accLog;
__device__ float g_sumU2;
__device__ float g_sumM2;

// ---------------- helpers ----------------
__device__ __forceinline__ float decode_pw(const void* p) {
    int v0 = ((const int*)p)[0];
    if (v0 > 0 && v0 < (1 << 26)) return (float)v0;
    float f = __int_as_float(v0);
    if (f > 0.0f && f < 1e8f) return f;
    return 0.0f;
}
__device__ __forceinline__ unsigned smem_u32(const void* p) {
    return (unsigned)__cvta_generic_to_shared(p);
}
__device__ __forceinline__ float ex2f(float x) {
    float y; asm("ex2.approx.f32 %0, %1;" : "=f"(y) : "f"(x)); return y;
}
__device__ __forceinline__ void mbar_init(uint32_t a, uint32_t cnt) {
    asm volatile("mbarrier.init.shared.b64 [%0], %1;" :: "r"(a), "r"(cnt) : "memory");
}
__device__ __forceinline__ void mbar_expect_tx(uint32_t a, uint32_t bytes) {
    asm volatile("mbarrier.arrive.expect_tx.shared.b64 _, [%0], %1;" :: "r"(a), "r"(bytes) : "memory");
}
__device__ __forceinline__ void mbar_wait(uint32_t a, uint32_t parity) {
    asm volatile(
        "{\n\t.reg .pred P;\n\t"
        "WL_%=:\n\t"
        "mbarrier.try_wait.parity.acquire.cta.shared::cta.b64 P, [%0], %1, 0x989680;\n\t"
        "@P bra.uni WD_%=;\n\t"
        "bra.uni WL_%=;\n\t"
        "WD_%=:\n\t}"
        :: "r"(a), "r"(parity) : "memory");
}
__device__ __forceinline__ void bulk_g2s(uint32_t dst, const void* src, uint32_t bytes, uint32_t mbar) {
    asm volatile("cp.async.bulk.shared::cluster.global.mbarrier::complete_tx::bytes [%0], [%1], %2, [%3];"
                 :: "r"(dst), "l"(src), "r"(bytes), "r"(mbar) : "memory");
}
__device__ __forceinline__ void ldm_x4(unsigned addr, unsigned &r0, unsigned &r1, unsigned &r2, unsigned &r3) {
    asm volatile("ldmatrix.sync.aligned.m8n8.x4.shared.b16 {%0,%1,%2,%3}, [%4];"
                 : "=r"(r0), "=r"(r1), "=r"(r2), "=r"(r3) : "r"(addr));
}
__device__ __forceinline__ void ldm_x4_t(unsigned addr, unsigned &r0, unsigned &r1, unsigned &r2, unsigned &r3) {
    asm volatile("ldmatrix.sync.aligned.m8n8.x4.trans.shared.b16 {%0,%1,%2,%3}, [%4];"
                 : "=r"(r0), "=r"(r1), "=r"(r2), "=r"(r3) : "r"(addr));
}
__device__ __forceinline__ void ldm_x2_t(unsigned addr, unsigned &r0, unsigned &r1) {
    asm volatile("ldmatrix.sync.aligned.m8n8.x2.trans.shared.b16 {%0,%1}, [%2];"
                 : "=r"(r0), "=r"(r1) : "r"(addr));
}
__device__ __forceinline__ void mma16816(float &c0, float &c1, float &c2, float &c3,
                                         unsigned a0, unsigned a1, unsigned a2, unsigned a3,
                                         unsigned b0, unsigned b1) {
    asm volatile("mma.sync.aligned.m16n8k16.row.col.f32.bf16.bf16.f32 "
                 "{%0,%1,%2,%3},{%4,%5,%6,%7},{%8,%9},{%0,%1,%2,%3};"
                 : "+f"(c0), "+f"(c1), "+f"(c2), "+f"(c3)
                 : "r"(a0), "r"(a1), "r"(a2), "r"(a3), "r"(b0), "r"(b1));
}
// fp8 mma with f16 accumulator
__device__ __forceinline__ void mma16832h(unsigned &c0, unsigned &c1,
                                          unsigned a0, unsigned a1, unsigned a2, unsigned a3,
                                          unsigned b0, unsigned b1) {
    asm volatile("mma.sync.aligned.m16n8k32.row.col.f16.e4m3.e4m3.f16 "
                 "{%0,%1},{%2,%3,%4,%5},{%6,%7},{%0,%1};"
                 : "+r"(c0), "+r"(c1)
                 : "r"(a0), "r"(a1), "r"(a2), "r"(a3), "r"(b0), "r"(b1));
}
__device__ __forceinline__ uint16_t fp8pair(float lo, float hi) {
    uint16_t r;
    asm("cvt.rn.satfinite.e4m3x2.f32 %0, %1, %2;" : "=h"(r) : "f"(hi), "f"(lo));
    return r;
}

// ---------------- kernels ----------------
// fused zero + label decode
__global__ void k_init(const int* __restrict__ p) {
    __shared__ int is64;
    if (threadIdx.x == 0) {
        int any = 0;
        #pragma unroll
        for (int i = 1; i < 128; i += 2) any |= p[i];
        is64 = (any == 0) ? 1 : 0;
    }
    __syncthreads();
    int s64 = is64;
    int i = blockIdx.x * 256 + threadIdx.x;
    if (i < B_SZ) {
        g_rowsumE[i] = 0.f;
        g_labels[i] = s64 ? p[2 * i] : p[i];
    }
    if (i < C_SZ) { g_Ssum[i] = 0.f; g_hist[i] = 0; }
    if (i == 0) { g_diagsum = 0.f; g_accLog = 0.f; g_sumU2 = 0.f; g_sumM2 = 0.f; }
}

// one-pass normalize: bf16 row-major + e4m3 (tile,kt)-chunk SW128 layout
__global__ __launch_bounds__(256) void k_norm(const float* __restrict__ reps, const float* __restrict__ soft) {
    int row = blockIdx.x;
    float4 v = ((const float4*)(reps + (size_t)row * D_SZ))[threadIdx.x];
    float ss = v.x * v.x + v.y * v.y + v.z * v.z + v.w * v.w;
    __shared__ float red[8];
    #pragma unroll
    for (int o = 16; o; o >>= 1) ss += __shfl_xor_sync(~0u, ss, o);
    if ((threadIdx.x & 31) == 0) red[threadIdx.x >> 5] = ss;
    __syncthreads();
    float sumsq = red[0] + red[1] + red[2] + red[3] + red[4] + red[5] + red[6] + red[7];
    float inv = 1.0f / fmaxf(sqrtf(sumsq), 1e-8f);
    float sc = inv * RNSCALE;
    __nv_bfloat162 p0 = __floats2bfloat162_rn(v.x * sc, v.y * sc);
    __nv_bfloat162 p1 = __floats2bfloat162_rn(v.z * sc, v.w * sc);
    uint2 pk; pk.x = *(uint32_t*)&p0; pk.y = *(uint32_t*)&p1;
    ((uint2*)(g_rn + (size_t)row * D_SZ))[threadIdx.x] = pk;
    float sq = inv * QSCALE;
    uint32_t q = (uint32_t)fp8pair(v.x * sq, v.y * sq)
               | ((uint32_t)fp8pair(v.z * sq, v.w * sq) << 16);
    {   // chunked + SW128-swizzled fp8 store (128B rows)
        int tile = row >> 7, lrow = row & 127;
        int ktc = threadIdx.x >> 5;               // col/128
        unsigned cb = (threadIdx.x & 31) * 4;     // byte within 128B chunk row
        unsigned quad = (cb >> 4) ^ ((unsigned)lrow & 7u);
        unsigned off = ((unsigned)lrow << 7) | (quad << 4) | (cb & 15);
        *(uint32_t*)(g_rq + ((size_t)(tile * KT_G + ktc) << 14) + off) = q;
    }
    if (threadIdx.x == 0) {
        atomicAdd(&g_diagsum, sumsq * inv * inv);
        atomicAdd(&g_hist[g_labels[row]], 1);
    }
    if (threadIdx.x < C_SZ) atomicAdd(&g_Ssum[threadIdx.x], soft[(size_t)row * C_SZ + threadIdx.x]);
}

// [U|M] = RN^T @ [soft | onehot] (scaled by RNSCALE), bf16 mma, split-k partials
__global__ __launch_bounds__(256) void k_small(const float* __restrict__ soft) {
    __shared__ __align__(16) __nv_bfloat16 rn_s[32][136];
    __shared__ __align__(16) __nv_bfloat16 sn_s[32][72];

    int mtile = blockIdx.x;   // 0..7
    int split = blockIdx.y;   // 0..KSPLIT-1
    int dbase = mtile * 128;
    int tid = threadIdx.x, lane = tid & 31, wid = tid >> 5;
    int wd = wid & 3, wn = wid >> 2;

    float acc[2][4][4];
    #pragma unroll
    for (int a = 0; a < 2; a++)
        #pragma unroll
        for (int b = 0; b < 4; b++)
            #pragma unroll
            for (int c = 0; c < 4; c++) acc[a][b][c] = 0.f;

    for (int ks = 0; ks < KCH / 32; ks++) {
        int i0 = split * KCH + ks * 32;
        #pragma unroll
        for (int j = 0; j < 2; j++) {
            int idx = tid + 256 * j;
            int row = idx >> 4, seg = idx & 15;
            *(uint4*)&rn_s[row][seg * 8] =
                *(const uint4*)(g_rn + (size_t)(i0 + row) * D_SZ + dbase + seg * 8);
        }
        {
            int i = tid >> 3, q = tid & 7;
            float4 sv = *(const float4*)(soft + (size_t)(i0 + i) * C_SZ + q * 4);
            __nv_bfloat162 p0 = __floats2bfloat162_rn(sv.x, sv.y);
            __nv_bfloat162 p1 = __floats2bfloat162_rn(sv.z, sv.w);
            uint2 pk; pk.x = *(uint32_t*)&p0; pk.y = *(uint32_t*)&p1;
            *(uint2*)&sn_s[i][q * 4] = pk;
            int lbl = g_labels[i0 + i];
            int n0 = q * 4;
            #pragma unroll
            for (int k = 0; k < 4; k++)
                sn_s[i][32 + n0 + k] = __float2bfloat16((lbl == n0 + k) ? 1.0f : 0.0f);
        }
        __syncthreads();

        unsigned a[2][2][4];
        #pragma unroll
        for (int mi = 0; mi < 2; mi++)
            #pragma unroll
            for (int kg = 0; kg < 2; kg++) {
                int krow = kg * 16 + (lane & 7) + ((lane >> 4) << 3);
                int mcol = wd * 32 + mi * 16 + ((lane >> 3) & 1) * 8;
                ldm_x4_t(smem_u32(&rn_s[krow][mcol]),
                         a[mi][kg][0], a[mi][kg][1], a[mi][kg][2], a[mi][kg][3]);
            }
        unsigned b[4][2][2];
        #pragma unroll
        for (int ni = 0; ni < 4; ni++)
            #pragma unroll
            for (int kg = 0; kg < 2; kg++) {
                int krow = kg * 16 + (lane & 15);
                ldm_x2_t(smem_u32(&sn_s[krow][wn * 32 + ni * 8]),
                         b[ni][kg][0], b[ni][kg][1]);
            }
        #pragma unroll
        for (int kg = 0; kg < 2; kg++)
            #pragma unroll
            for (int mi = 0; mi < 2; mi++)
                #pragma unroll
                for (int ni = 0; ni < 4; ni++)
                    mma16816(acc[mi][ni][0], acc[mi][ni][1], acc[mi][ni][2], acc[mi][ni][3],
                             a[mi][kg][0], a[mi][kg][1], a[mi][kg][2], a[mi][kg][3],
                             b[ni][kg][0], b[ni][kg][1]);
        __syncthreads();
    }

    #pragma unroll
    for (int mi = 0; mi < 2; mi++)
        #pragma unroll
        for (int ni = 0; ni < 4; ni++)
            #pragma unroll
            for (int r = 0; r < 4; r++) {
                int row = (lane >> 2) + (r >> 1) * 8;
                int col = (lane & 3) * 2 + (r & 1);
                int dl = wd * 32 + mi * 16 + row;
                int n  = wn * 32 + ni * 8 + col;
                g_part[((size_t)(split * 8 + mtile) * 128 + dl) * NSM + n] = acc[mi][ni][r];
            }
}

// swizzled smem address within a 128B-row chunk: (row, 16B-quad qi)
__device__ __forceinline__ unsigned swz_addr(unsigned base, int row, int qi) {
    unsigned q = ((unsigned)qi ^ ((unsigned)row & 7u)) & 7u;
    return base + ((unsigned)row << 7) + (q << 4);
}

// main pass: fp8 e4m3 mma (f16 acc), triangular 128x128 tiles,
// cp.async.bulk 16KB chunks + 3-stage mbarrier ring, fragment double-buffering, 2 CTA/SM
__global__ __launch_bounds__(256, 2) void k_gemm_q() {
    extern __shared__ __align__(128) uint8_t smem[];
    const unsigned sb = smem_u32(smem);
    float* rowbuf = (float*)(smem + SM_ROW);
    float* colbuf = (float*)(smem + SM_COL);

    int idx = blockIdx.x;
    int I = 0;
    while (idx >= (TTOT - I)) { idx -= (TTOT - I); ++I; }
    int J = I + idx;
    bool diag = (I == J);

    int tid = threadIdx.x;
    int wid = tid >> 5, lane = tid & 31;
    int wm = wid & 1, wn = wid >> 1;       // 2x4 warps, 64x32 warp tiles

    if (tid < BM) { rowbuf[tid] = 0.f; colbuf[tid] = 0.f; }

    const uint8_t* gA = g_rq + ((size_t)I * KT_G << 14);
    const uint8_t* gB = g_rq + ((size_t)J * KT_G << 14);

    if (tid == 0) {
        #pragma unroll
        for (int s = 0; s < 3; s++) mbar_init(sb + SM_MB + s * 8, 1);
    }
    __syncthreads();
    if (tid == 0) {
        #pragma unroll
        for (int p = 0; p < 2; p++) {
            unsigned mb = sb + SM_MB + p * 8;
            mbar_expect_tx(mb, 2 * CHUNK);
            bulk_g2s(sb + SM_AB(p),         gA + p * CHUNK, CHUNK, mb);
            bulk_g2s(sb + SM_AB(p) + CHUNK, gB + p * CHUNK, CHUNK, mb);
        }
    }

    unsigned acc[4][4][2];
    #pragma unroll
    for (int a = 0; a < 4; a++)
        #pragma unroll
        for (int b = 0; b < 4; b++) { acc[a][b][0] = 0u; acc[a][b][1] = 0u; }

    const int arow0 = wm * 64 + (lane & 15);
    const int aq0   = lane >> 4;
    const int brow0 = wn * 32 + ((lane >> 4) << 3) + (lane & 7);
    const int bq0   = (lane >> 3) & 1;

    int st = 0, ph = 0;        // consumer stage cursor
    int pst = 2;               // producer stage cursor (fills kt+2)
    for (int kt = 0; kt < KT_G; ++kt) {
        if (kt) __syncthreads();            // all warps done reading the stage being refilled
        if (tid == 0 && kt + 2 < KT_G) {
            unsigned mb = sb + SM_MB + pst * 8;
            mbar_expect_tx(mb, 2 * CHUNK);
            bulk_g2s(sb + SM_AB(pst),         gA + (kt + 2) * CHUNK, CHUNK, mb);
            bulk_g2s(sb + SM_AB(pst) + CHUNK, gB + (kt + 2) * CHUNK, CHUNK, mb);
        }
        if (++pst == 3) pst = 0;
        mbar_wait(sb + SM_MB + st * 8, ph);
        unsigned aBase = sb + SM_AB(st);
        unsigned bBase = aBase + CHUNK;

        unsigned fa[2][4][4], fb[2][4][2];
        // load s=0 fragments
        #pragma unroll
        for (int mi = 0; mi < 4; mi++)
            ldm_x4(swz_addr(aBase, arow0 + mi * 16, aq0),
                   fa[0][mi][0], fa[0][mi][1], fa[0][mi][2], fa[0][mi][3]);
        #pragma unroll
        for (int nj = 0; nj < 2; nj++)
            ldm_x4(swz_addr(bBase, brow0 + nj * 16, bq0),
                   fb[0][2 * nj][0], fb[0][2 * nj][1], fb[0][2 * nj + 1][0], fb[0][2 * nj + 1][1]);
        #pragma unroll
        for (int s = 0; s < 4; s++) {
            int cur = s & 1, nxt = cur ^ 1;
            if (s < 3) {   // prefetch s+1 fragments before the MMAs of s
                #pragma unroll
                for (int mi = 0; mi < 4; mi++)
                    ldm_x4(swz_addr(aBase, arow0 + mi * 16, (s + 1) * 2 + aq0),
                           fa[nxt][mi][0], fa[nxt][mi][1], fa[nxt][mi][2], fa[nxt][mi][3]);
                #pragma unroll
                for (int nj = 0; nj < 2; nj++)
                    ldm_x4(swz_addr(bBase, brow0 + nj * 16, (s + 1) * 2 + bq0),
                           fb[nxt][2 * nj][0], fb[nxt][2 * nj][1],
                           fb[nxt][2 * nj + 1][0], fb[nxt][2 * nj + 1][1]);
            }
            #pragma unroll
            for (int mi = 0; mi < 4; mi++)
                #pragma unroll
                for (int ni = 0; ni < 4; ni++)
                    mma16832h(acc[mi][ni][0], acc[mi][ni][1],
                              fa[cur][mi][0], fa[cur][mi][1], fa[cur][mi][2], fa[cur][mi][3],
                              fb[cur][ni][0], fb[cur][ni][1]);
        }
        if (++st == 3) { st = 0; ph ^= 1; }
    }

    // epilogue: e = 2^(acc*QC); row sums (I) and col sums (J)
    int g = lane >> 2, t = lane & 3;
    int rbase = wm * 64, cbase = wn * 32;
    float colp[4][2];
    #pragma unroll
    for (int ni = 0; ni < 4; ni++) { colp[ni][0] = 0.f; colp[ni][1] = 0.f; }

    #pragma unroll
    for (int mi = 0; mi < 4; mi++) {
        float r0 = 0.f, r1 = 0.f;
        #pragma unroll
        for (int ni = 0; ni < 4; ni++) {
            float2 f0 = __half22float2(*(__half2*)&acc[mi][ni][0]);   // row g,   cols 2t,2t+1
            float2 f1 = __half22float2(*(__half2*)&acc[mi][ni][1]);   // row g+8, cols 2t,2t+1
            float e0 = ex2f(f0.x * QC);
            float e1 = ex2f(f0.y * QC);
            float e2 = ex2f(f1.x * QC);
            float e3 = ex2f(f1.y * QC);
            if (diag) {
                int r = rbase + mi * 16 + g, c = cbase + ni * 8 + t * 2;
                if (r == c)     e0 = 0.f;
                if (r == c + 1) e1 = 0.f;
                if (r + 8 == c)     e2 = 0.f;
                if (r + 8 == c + 1) e3 = 0.f;
            }
            r0 += e0 + e1; r1 += e2 + e3;
            colp[ni][0] += e0 + e2; colp[ni][1] += e1 + e3;
        }
        r0 += __shfl_xor_sync(~0u, r0, 1); r0 += __shfl_xor_sync(~0u, r0, 2);
        r1 += __shfl_xor_sync(~0u, r1, 1); r1 += __shfl_xor_sync(~0u, r1, 2);
        if (t == 0) {
            atomicAdd(&rowbuf[rbase + mi * 16 + g],     r0);
            atomicAdd(&rowbuf[rbase + mi * 16 + g + 8], r1);
        }
    }
    if (!diag) {
        #pragma unroll
        for (int ni = 0; ni < 4; ni++) {
            #pragma unroll
            for (int p = 0; p < 2; p++) {
                float v = colp[ni][p];
                v += __shfl_xor_sync(~0u, v, 4);
                v += __shfl_xor_sync(~0u, v, 8);
                v += __shfl_xor_sync(~0u, v, 16);
                if (lane < 4) atomicAdd(&colbuf[cbase + ni * 8 + lane * 2 + p], v);
            }
        }
    }
    __syncthreads();
    if (tid < BM) {
        atomicAdd(&g_rowsumE[I * BM + tid], rowbuf[tid]);
        if (!diag) atomicAdd(&g_rowsumE[J * BN + tid], colbuf[tid]);
    }
}

// fused: blocks [0,256) reduce split-k partials; blocks [256,272) row terms
__global__ void k_tail(const float* __restrict__ soft, const void* pwp) {
    if (blockIdx.x < 256) {
        int idx = blockIdx.x * 256 + threadIdx.x;
        float su = 0.f, sm = 0.f;
        {
            int d = idx >> 6, n = idx & 63;
            int mt = d >> 7, dl = d & 127;
            float s = 0.f;
            #pragma unroll
            for (int sp = 0; sp < KSPLIT; sp++)
                s += g_part[((size_t)(sp * 8 + mt) * 128 + dl) * NSM + n];
            if (n < C_SZ) su = s * s; else sm = s * s;
        }
        #pragma unroll
        for (int o = 16; o; o >>= 1) { su += __shfl_xor_sync(~0u, su, o); sm += __shfl_xor_sync(~0u, sm, o); }
        __shared__ float rs[8], rm[8];
        if ((threadIdx.x & 31) == 0) { rs[threadIdx.x >> 5] = su; rm[threadIdx.x >> 5] = sm; }
        __syncthreads();
        if (threadIdx.x < 8) {
            float a = rs[threadIdx.x], b = rm[threadIdx.x];
            #pragma unroll
            for (int o = 4; o; o >>= 1) { a += __shfl_xor_sync(0xff, a, o); b += __shfl_xor_sync(0xff, b, o); }
            if (threadIdx.x == 0) { atomicAdd(&g_sumU2, a); atomicAdd(&g_sumM2, b); }
        }
    } else {
        float pw = decode_pw(pwp);
        int i = (blockIdx.x - 256) * 256 + threadIdx.x;
        float term = 0.f;
        {
            int lbl = g_labels[i];
            float wsum = (float)(g_hist[lbl] - 1);
            const float* s = soft + (size_t)i * C_SZ;
            float d = 0.f;
            #pragma unroll
            for (int c = 0; c < C_SZ; c++) d += s[c] * g_Ssum[c];
            wsum += pw * d;
            term = wsum * logf(g_rowsumE[i]);
        }
        #pragma unroll
        for (int o = 16; o; o >>= 1) term += __shfl_xor_sync(~0u, term, o);
        __shared__ float red[8];
        if ((threadIdx.x & 31) == 0) red[threadIdx.x >> 5] = term;
        __syncthreads();
        if (threadIdx.x < 8) {
            float v = red[threadIdx.x];
            #pragma unroll
            for (int o = 4; o; o >>= 1) v += __shfl_xor_sync(0xff, v, o);
            if (threadIdx.x == 0) atomicAdd(&g_accLog, v);
        }
    }
}

__global__ void k_out(float* out, const void* pwp) {
    float pw = decode_pw(pwp);
    float P  = (g_sumM2 * S2INV - g_diagsum) * 10.0f;
    float SZ = (g_sumU2 * S2INV) * 10.0f;
    out[0] = (g_accLog - P - pw * SZ) / (float)B_SZ;
}

// ---------------- launch ----------------
extern "C" void kernel_launch(void* const* d_in, const int* in_sizes, int n_in,
                              void* d_out, int out_size) {
    const float* reps = (const float*)d_in[0];
    const float* soft = (const float*)d_in[1];
    const int*   lblp = (const int*)d_in[2];
    const void*  pwp  = d_in[3];
    float* out = (float*)d_out;
    (void)in_sizes; (void)n_in; (void)out_size;

    cudaFuncSetAttribute(k_gemm_q, cudaFuncAttributeMaxDynamicSharedMemorySize, SM_TOT);

    k_init<<<16, 256>>>(lblp);
    k_norm<<<B_SZ, 256>>>(reps, soft);
    k_small<<<dim3(8, KSPLIT), 256>>>(soft);
    k_gemm_q<<<NPAIR, 256, SM_TOT>>>();
    k_tail<<<272, 256>>>(soft, pwp);
    k_out<<<1, 1>>>(out, pwp);
}

// round 16
// speedup vs baseline: 1.3708x; 1.0769x over previous
#include <cuda_runtime.h>
#include <cuda_bf16.h>
#include <cuda_fp16.h>
#include <cuda_fp8.h>
#include <cstdint>

#define B_SZ 4096
#define D_SZ 1024
#define C_SZ 32
// bf16 rn scaled by sqrt(10*log2(e)); U/M sums divided by S2 later
#define RNSCALE 3.7982825500f
#define S2INV   (1.0f/14.4269504089f)
// fp8 rn scaled by 16; epilogue: exp(10 z) = 2^(acc * QC), QC = 10*log2(e)/256
#define QSCALE  16.0f
#define QC      0.05635527503472513f

#define BM 128
#define BN 128
#define TTOT (B_SZ/BM)    // 32
#define NPAIR (TTOT*(TTOT+1)/2)  // 528
#define KT_G 8            // k-chunks of 128 fp8
#define CHUNK 16384       // one (tile, kt) chunk: 128 rows x 128B, SW128 swizzled

// dynamic smem layout (3-stage ring for gemm path; small path reuses front)
#define SM_AB(s)  ((s) * 32768)          // A at +0 (16KB), B at +16384
#define SM_MB     98304                   // 3 mbarriers
#define SM_ROW    98368
#define SM_COL    98880
#define SM_TOT    99392

// small GEMM (U|M): RN^T [1024 x 4096] @ [soft | onehot] [4096 x 64]
#define KSPLIT 64
#define KCH (B_SZ/KSPLIT)   // 64
#define NSM 64
#define NSMALL (8 * KSPLIT) // 512 blocks

// ---------------- device scratch ----------------
__device__ __align__(128) __nv_bfloat16 g_rn[B_SZ * D_SZ];   // bf16, scale RNSCALE
__device__ __align__(128) uint8_t       g_rq[B_SZ * D_SZ];   // e4m3, (tile,kt)-chunk SW128 layout
__device__ float g_rowsumE[B_SZ];
__device__ float g_part[KSPLIT * 8 * 128 * NSM];   // split-k partials
__device__ float g_Ssum[C_SZ];
__device__ int   g_hist[C_SZ];
__device__ int   g_labels[B_SZ];
__device__ float g_diagsum;
__device__ float g_accLog;
__device__ float g_sumU2;
__device__ float g_sumM2;
__device__ unsigned g_done;

// ---------------- helpers ----------------
__device__ __forceinline__ float decode_pw(const void* p) {
    int v0 = ((const int*)p)[0];
    if (v0 > 0 && v0 < (1 << 26)) return (float)v0;
    float f = __int_as_float(v0);
    if (f > 0.0f && f < 1e8f) return f;
    return 0.0f;
}
__device__ __forceinline__ unsigned smem_u32(const void* p) {
    return (unsigned)__cvta_generic_to_shared(p);
}
__device__ __forceinline__ float ex2f(float x) {
    float y; asm("ex2.approx.f32 %0, %1;" : "=f"(y) : "f"(x)); return y;
}
__device__ __forceinline__ void mbar_init(uint32_t a, uint32_t cnt) {
    asm volatile("mbarrier.init.shared.b64 [%0], %1;" :: "r"(a), "r"(cnt) : "memory");
}
__device__ __forceinline__ void mbar_expect_tx(uint32_t a, uint32_t bytes) {
    asm volatile("mbarrier.arrive.expect_tx.shared.b64 _, [%0], %1;" :: "r"(a), "r"(bytes) : "memory");
}
__device__ __forceinline__ void mbar_wait(uint32_t a, uint32_t parity) {
    asm volatile(
        "{\n\t.reg .pred P;\n\t"
        "WL_%=:\n\t"
        "mbarrier.try_wait.parity.acquire.cta.shared::cta.b64 P, [%0], %1, 0x989680;\n\t"
        "@P bra.uni WD_%=;\n\t"
        "bra.uni WL_%=;\n\t"
        "WD_%=:\n\t}"
        :: "r"(a), "r"(parity) : "memory");
}
__device__ __forceinline__ void bulk_g2s(uint32_t dst, const void* src, uint32_t bytes, uint32_t mbar) {
    asm volatile("cp.async.bulk.shared::cluster.global.mbarrier::complete_tx::bytes [%0], [%1], %2, [%3];"
                 :: "r"(dst), "l"(src), "r"(bytes), "r"(mbar) : "memory");
}
__device__ __forceinline__ void ldm_x4(unsigned addr, unsigned &r0, unsigned &r1, unsigned &r2, unsigned &r3) {
    asm volatile("ldmatrix.sync.aligned.m8n8.x4.shared.b16 {%0,%1,%2,%3}, [%4];"
                 : "=r"(r0), "=r"(r1), "=r"(r2), "=r"(r3) : "r"(addr));
}
__device__ __forceinline__ void ldm_x4_t(unsigned addr, unsigned &r0, unsigned &r1, unsigned &r2, unsigned &r3) {
    asm volatile("ldmatrix.sync.aligned.m8n8.x4.trans.shared.b16 {%0,%1,%2,%3}, [%4];"
                 : "=r"(r0), "=r"(r1), "=r"(r2), "=r"(r3) : "r"(addr));
}
__device__ __forceinline__ void ldm_x2_t(unsigned addr, unsigned &r0, unsigned &r1) {
    asm volatile("ldmatrix.sync.aligned.m8n8.x2.trans.shared.b16 {%0,%1}, [%2];"
                 : "=r"(r0), "=r"(r1) : "r"(addr));
}
__device__ __forceinline__ void mma16816(float &c0, float &c1, float &c2, float &c3,
                                         unsigned a0, unsigned a1, unsigned a2, unsigned a3,
                                         unsigned b0, unsigned b1) {
    asm volatile("mma.sync.aligned.m16n8k16.row.col.f32.bf16.bf16.f32 "
                 "{%0,%1,%2,%3},{%4,%5,%6,%7},{%8,%9},{%0,%1,%2,%3};"
                 : "+f"(c0), "+f"(c1), "+f"(c2), "+f"(c3)
                 : "r"(a0), "r"(a1), "r"(a2), "r"(a3), "r"(b0), "r"(b1));
}
// fp8 mma with f16 accumulator
__device__ __forceinline__ void mma16832h(unsigned &c0, unsigned &c1,
                                          unsigned a0, unsigned a1, unsigned a2, unsigned a3,
                                          unsigned b0, unsigned b1) {
    asm volatile("mma.sync.aligned.m16n8k32.row.col.f16.e4m3.e4m3.f16 "
                 "{%0,%1},{%2,%3,%4,%5},{%6,%7},{%0,%1};"
                 : "+r"(c0), "+r"(c1)
                 : "r"(a0), "r"(a1), "r"(a2), "r"(a3), "r"(b0), "r"(b1));
}
__device__ __forceinline__ uint16_t fp8pair(float lo, float hi) {
    uint16_t r;
    asm("cvt.rn.satfinite.e4m3x2.f32 %0, %1, %2;" : "=h"(r) : "f"(hi), "f"(lo));
    return r;
}

// ---------------- kernels ----------------
// fused zero + label decode
__global__ void k_init(const int* __restrict__ p) {
    __shared__ int is64;
    if (threadIdx.x == 0) {
        int any = 0;
        #pragma unroll
        for (int i = 1; i < 128; i += 2) any |= p[i];
        is64 = (any == 0) ? 1 : 0;
    }
    __syncthreads();
    int s64 = is64;
    int i = blockIdx.x * 256 + threadIdx.x;
    if (i < B_SZ) {
        g_rowsumE[i] = 0.f;
        g_labels[i] = s64 ? p[2 * i] : p[i];
    }
    if (i < C_SZ) { g_Ssum[i] = 0.f; g_hist[i] = 0; }
    if (i == 0) { g_diagsum = 0.f; g_accLog = 0.f; g_sumU2 = 0.f; g_sumM2 = 0.f; g_done = 0u; }
}

// one-pass normalize: bf16 row-major + e4m3 (tile,kt)-chunk SW128 layout
__global__ __launch_bounds__(256) void k_norm(const float* __restrict__ reps, const float* __restrict__ soft) {
    int row = blockIdx.x;
    float4 v = ((const float4*)(reps + (size_t)row * D_SZ))[threadIdx.x];
    float ss = v.x * v.x + v.y * v.y + v.z * v.z + v.w * v.w;
    __shared__ float red[8];
    #pragma unroll
    for (int o = 16; o; o >>= 1) ss += __shfl_xor_sync(~0u, ss, o);
    if ((threadIdx.x & 31) == 0) red[threadIdx.x >> 5] = ss;
    __syncthreads();
    float sumsq = red[0] + red[1] + red[2] + red[3] + red[4] + red[5] + red[6] + red[7];
    float inv = 1.0f / fmaxf(sqrtf(sumsq), 1e-8f);
    float sc = inv * RNSCALE;
    __nv_bfloat162 p0 = __floats2bfloat162_rn(v.x * sc, v.y * sc);
    __nv_bfloat162 p1 = __floats2bfloat162_rn(v.z * sc, v.w * sc);
    uint2 pk; pk.x = *(uint32_t*)&p0; pk.y = *(uint32_t*)&p1;
    ((uint2*)(g_rn + (size_t)row * D_SZ))[threadIdx.x] = pk;
    float sq = inv * QSCALE;
    uint32_t q = (uint32_t)fp8pair(v.x * sq, v.y * sq)
               | ((uint32_t)fp8pair(v.z * sq, v.w * sq) << 16);
    {   // chunked + SW128-swizzled fp8 store (128B rows)
        int tile = row >> 7, lrow = row & 127;
        int ktc = threadIdx.x >> 5;               // col/128
        unsigned cb = (threadIdx.x & 31) * 4;     // byte within 128B chunk row
        unsigned quad = (cb >> 4) ^ ((unsigned)lrow & 7u);
        unsigned off = ((unsigned)lrow << 7) | (quad << 4) | (cb & 15);
        *(uint32_t*)(g_rq + ((size_t)(tile * KT_G + ktc) << 14) + off) = q;
    }
    if (threadIdx.x == 0) {
        atomicAdd(&g_diagsum, sumsq * inv * inv);
        atomicAdd(&g_hist[g_labels[row]], 1);
    }
    if (threadIdx.x < C_SZ) atomicAdd(&g_Ssum[threadIdx.x], soft[(size_t)row * C_SZ + threadIdx.x]);
}

// swizzled smem address within a 128B-row chunk: (row, 16B-quad qi)
__device__ __forceinline__ unsigned swz_addr(unsigned base, int row, int qi) {
    unsigned q = ((unsigned)qi ^ ((unsigned)row & 7u)) & 7u;
    return base + ((unsigned)row << 7) + (q << 4);
}

// ---- gemm path (blocks [0, NPAIR)) ----
__device__ void gemm_path(uint8_t* smem, int bidx) {
    const unsigned sb = smem_u32(smem);
    float* rowbuf = (float*)(smem + SM_ROW);
    float* colbuf = (float*)(smem + SM_COL);

    int idx = bidx;
    int I = 0;
    while (idx >= (TTOT - I)) { idx -= (TTOT - I); ++I; }
    int J = I + idx;
    bool diag = (I == J);

    int tid = threadIdx.x;
    int wid = tid >> 5, lane = tid & 31;
    int wm = wid & 1, wn = wid >> 1;       // 2x4 warps, 64x32 warp tiles

    if (tid < BM) { rowbuf[tid] = 0.f; colbuf[tid] = 0.f; }

    const uint8_t* gA = g_rq + ((size_t)I * KT_G << 14);
    const uint8_t* gB = g_rq + ((size_t)J * KT_G << 14);

    if (tid == 0) {
        #pragma unroll
        for (int s = 0; s < 3; s++) mbar_init(sb + SM_MB + s * 8, 1);
    }
    __syncthreads();
    if (tid == 0) {
        #pragma unroll
        for (int p = 0; p < 2; p++) {
            unsigned mb = sb + SM_MB + p * 8;
            mbar_expect_tx(mb, 2 * CHUNK);
            bulk_g2s(sb + SM_AB(p),         gA + p * CHUNK, CHUNK, mb);
            bulk_g2s(sb + SM_AB(p) + CHUNK, gB + p * CHUNK, CHUNK, mb);
        }
    }

    unsigned acc[4][4][2];
    #pragma unroll
    for (int a = 0; a < 4; a++)
        #pragma unroll
        for (int b = 0; b < 4; b++) { acc[a][b][0] = 0u; acc[a][b][1] = 0u; }

    const int arow0 = wm * 64 + (lane & 15);
    const int aq0   = lane >> 4;
    const int brow0 = wn * 32 + ((lane >> 4) << 3) + (lane & 7);
    const int bq0   = (lane >> 3) & 1;

    int st = 0, ph = 0;        // consumer stage cursor
    int pst = 2;               // producer stage cursor (fills kt+2)
    for (int kt = 0; kt < KT_G; ++kt) {
        if (kt) __syncthreads();            // all warps done reading the stage being refilled
        if (tid == 0 && kt + 2 < KT_G) {
            unsigned mb = sb + SM_MB + pst * 8;
            mbar_expect_tx(mb, 2 * CHUNK);
            bulk_g2s(sb + SM_AB(pst),         gA + (kt + 2) * CHUNK, CHUNK, mb);
            bulk_g2s(sb + SM_AB(pst) + CHUNK, gB + (kt + 2) * CHUNK, CHUNK, mb);
        }
        if (++pst == 3) pst = 0;
        mbar_wait(sb + SM_MB + st * 8, ph);
        unsigned aBase = sb + SM_AB(st);
        unsigned bBase = aBase + CHUNK;

        unsigned fa[2][4][4], fb[2][4][2];
        #pragma unroll
        for (int mi = 0; mi < 4; mi++)
            ldm_x4(swz_addr(aBase, arow0 + mi * 16, aq0),
                   fa[0][mi][0], fa[0][mi][1], fa[0][mi][2], fa[0][mi][3]);
        #pragma unroll
        for (int nj = 0; nj < 2; nj++)
            ldm_x4(swz_addr(bBase, brow0 + nj * 16, bq0),
                   fb[0][2 * nj][0], fb[0][2 * nj][1], fb[0][2 * nj + 1][0], fb[0][2 * nj + 1][1]);
        #pragma unroll
        for (int s = 0; s < 4; s++) {
            int cur = s & 1, nxt = cur ^ 1;
            if (s < 3) {
                #pragma unroll
                for (int mi = 0; mi < 4; mi++)
                    ldm_x4(swz_addr(aBase, arow0 + mi * 16, (s + 1) * 2 + aq0),
                           fa[nxt][mi][0], fa[nxt][mi][1], fa[nxt][mi][2], fa[nxt][mi][3]);
                #pragma unroll
                for (int nj = 0; nj < 2; nj++)
                    ldm_x4(swz_addr(bBase, brow0 + nj * 16, (s + 1) * 2 + bq0),
                           fb[nxt][2 * nj][0], fb[nxt][2 * nj][1],
                           fb[nxt][2 * nj + 1][0], fb[nxt][2 * nj + 1][1]);
            }
            #pragma unroll
            for (int mi = 0; mi < 4; mi++)
                #pragma unroll
                for (int ni = 0; ni < 4; ni++)
                    mma16832h(acc[mi][ni][0], acc[mi][ni][1],
                              fa[cur][mi][0], fa[cur][mi][1], fa[cur][mi][2], fa[cur][mi][3],
                              fb[cur][ni][0], fb[cur][ni][1]);
        }
        if (++st == 3) { st = 0; ph ^= 1; }
    }

    // epilogue: e = 2^(acc*QC); row sums (I) and col sums (J)
    int g = lane >> 2, t = lane & 3;
    int rbase = wm * 64, cbase = wn * 32;
    float colp[4][2];
    #pragma unroll
    for (int ni = 0; ni < 4; ni++) { colp[ni][0] = 0.f; colp[ni][1] = 0.f; }

    #pragma unroll
    for (int mi = 0; mi < 4; mi++) {
        float r0 = 0.f, r1 = 0.f;
        #pragma unroll
        for (int ni = 0; ni < 4; ni++) {
            float2 f0 = __half22float2(*(__half2*)&acc[mi][ni][0]);
            float2 f1 = __half22float2(*(__half2*)&acc[mi][ni][1]);
            float e0 = ex2f(f0.x * QC);
            float e1 = ex2f(f0.y * QC);
            float e2 = ex2f(f1.x * QC);
            float e3 = ex2f(f1.y * QC);
            if (diag) {
                int r = rbase + mi * 16 + g, c = cbase + ni * 8 + t * 2;
                if (r == c)     e0 = 0.f;
                if (r == c + 1) e1 = 0.f;
                if (r + 8 == c)     e2 = 0.f;
                if (r + 8 == c + 1) e3 = 0.f;
            }
            r0 += e0 + e1; r1 += e2 + e3;
            colp[ni][0] += e0 + e2; colp[ni][1] += e1 + e3;
        }
        r0 += __shfl_xor_sync(~0u, r0, 1); r0 += __shfl_xor_sync(~0u, r0, 2);
        r1 += __shfl_xor_sync(~0u, r1, 1); r1 += __shfl_xor_sync(~0u, r1, 2);
        if (t == 0) {
            atomicAdd(&rowbuf[rbase + mi * 16 + g],     r0);
            atomicAdd(&rowbuf[rbase + mi * 16 + g + 8], r1);
        }
    }
    if (!diag) {
        #pragma unroll
        for (int ni = 0; ni < 4; ni++) {
            #pragma unroll
            for (int p = 0; p < 2; p++) {
                float v = colp[ni][p];
                v += __shfl_xor_sync(~0u, v, 4);
                v += __shfl_xor_sync(~0u, v, 8);
                v += __shfl_xor_sync(~0u, v, 16);
                if (lane < 4) atomicAdd(&colbuf[cbase + ni * 8 + lane * 2 + p], v);
            }
        }
    }
    __syncthreads();
    if (tid < BM) {
        atomicAdd(&g_rowsumE[I * BM + tid], rowbuf[tid]);
        if (!diag) atomicAdd(&g_rowsumE[J * BN + tid], colbuf[tid]);
    }
}

// ---- small path (blocks [NPAIR, NPAIR+NSMALL)): [U|M] = RN^T @ [soft|onehot] ----
__device__ void small_path(uint8_t* smem, const float* __restrict__ soft, int sidx) {
    __nv_bfloat16 (*rn_s)[136] = (__nv_bfloat16(*)[136])(smem);          // 32x136 bf16 = 8704B
    __nv_bfloat16 (*sn_s)[72]  = (__nv_bfloat16(*)[72])(smem + 8704);    // 32x72  bf16 = 4608B

    int mtile = sidx & 7;       // 0..7
    int split = sidx >> 3;      // 0..KSPLIT-1
    int dbase = mtile * 128;
    int tid = threadIdx.x, lane = tid & 31, wid = tid >> 5;
    int wd = wid & 3, wn = wid >> 2;

    float acc[2][4][4];
    #pragma unroll
    for (int a = 0; a < 2; a++)
        #pragma unroll
        for (int b = 0; b < 4; b++)
            #pragma unroll
            for (int c = 0; c < 4; c++) acc[a][b][c] = 0.f;

    for (int ks = 0; ks < KCH / 32; ks++) {
        int i0 = split * KCH + ks * 32;
        #pragma unroll
        for (int j = 0; j < 2; j++) {
            int idx = tid + 256 * j;
            int row = idx >> 4, seg = idx & 15;
            *(uint4*)&rn_s[row][seg * 8] =
                *(const uint4*)(g_rn + (size_t)(i0 + row) * D_SZ + dbase + seg * 8);
        }
        {
            int i = tid >> 3, q = tid & 7;
            float4 sv = *(const float4*)(soft + (size_t)(i0 + i) * C_SZ + q * 4);
            __nv_bfloat162 p0 = __floats2bfloat162_rn(sv.x, sv.y);
            __nv_bfloat162 p1 = __floats2bfloat162_rn(sv.z, sv.w);
            uint2 pk; pk.x = *(uint32_t*)&p0; pk.y = *(uint32_t*)&p1;
            *(uint2*)&sn_s[i][q * 4] = pk;
            int lbl = g_labels[i0 + i];
            int n0 = q * 4;
            #pragma unroll
            for (int k = 0; k < 4; k++)
                sn_s[i][32 + n0 + k] = __float2bfloat16((lbl == n0 + k) ? 1.0f : 0.0f);
        }
        __syncthreads();

        unsigned a[2][2][4];
        #pragma unroll
        for (int mi = 0; mi < 2; mi++)
            #pragma unroll
            for (int kg = 0; kg < 2; kg++) {
                int krow = kg * 16 + (lane & 7) + ((lane >> 4) << 3);
                int mcol = wd * 32 + mi * 16 + ((lane >> 3) & 1) * 8;
                ldm_x4_t(smem_u32(&rn_s[krow][mcol]),
                         a[mi][kg][0], a[mi][kg][1], a[mi][kg][2], a[mi][kg][3]);
            }
        unsigned b[4][2][2];
        #pragma unroll
        for (int ni = 0; ni < 4; ni++)
            #pragma unroll
            for (int kg = 0; kg < 2; kg++) {
                int krow = kg * 16 + (lane & 15);
                ldm_x2_t(smem_u32(&sn_s[krow][wn * 32 + ni * 8]),
                         b[ni][kg][0], b[ni][kg][1]);
            }
        #pragma unroll
        for (int kg = 0; kg < 2; kg++)
            #pragma unroll
            for (int mi = 0; mi < 2; mi++)
                #pragma unroll
                for (int ni = 0; ni < 4; ni++)
                    mma16816(acc[mi][ni][0], acc[mi][ni][1], acc[mi][ni][2], acc[mi][ni][3],
                             a[mi][kg][0], a[mi][kg][1], a[mi][kg][2], a[mi][kg][3],
                             b[ni][kg][0], b[ni][kg][1]);
        __syncthreads();
    }

    #pragma unroll
    for (int mi = 0; mi < 2; mi++)
        #pragma unroll
        for (int ni = 0; ni < 4; ni++)
            #pragma unroll
            for (int r = 0; r < 4; r++) {
                int row = (lane >> 2) + (r >> 1) * 8;
                int col = (lane & 3) * 2 + (r & 1);
                int dl = wd * 32 + mi * 16 + row;
                int n  = wn * 32 + ni * 8 + col;
                g_part[((size_t)(split * 8 + mtile) * 128 + dl) * NSM + n] = acc[mi][ni][r];
            }
}

// fused heterogeneous kernel
__global__ __launch_bounds__(256, 2) void k_fused(const float* __restrict__ soft) {
    extern __shared__ __align__(128) uint8_t smem[];
    if (blockIdx.x < NPAIR) gemm_path(smem, blockIdx.x);
    else                    small_path(smem, soft, blockIdx.x - NPAIR);
}

// fused tail: blocks [0,256) reduce split-k partials; [256,272) row terms; last block writes out
__global__ void k_tail(const float* __restrict__ soft, const void* pwp, float* out) {
    if (blockIdx.x < 256) {
        int idx = blockIdx.x * 256 + threadIdx.x;
        float su = 0.f, sm = 0.f;
        {
            int d = idx >> 6, n = idx & 63;
            int mt = d >> 7, dl = d & 127;
            float s = 0.f;
            #pragma unroll
            for (int sp = 0; sp < KSPLIT; sp++)
                s += g_part[((size_t)(sp * 8 + mt) * 128 + dl) * NSM + n];
            if (n < C_SZ) su = s * s; else sm = s * s;
        }
        #pragma unroll
        for (int o = 16; o; o >>= 1) { su += __shfl_xor_sync(~0u, su, o); sm += __shfl_xor_sync(~0u, sm, o); }
        __shared__ float rs[8], rm[8];
        if ((threadIdx.x & 31) == 0) { rs[threadIdx.x >> 5] = su; rm[threadIdx.x >> 5] = sm; }
        __syncthreads();
        if (threadIdx.x < 8) {
            float a = rs[threadIdx.x], b = rm[threadIdx.x];
            #pragma unroll
            for (int o = 4; o; o >>= 1) { a += __shfl_xor_sync(0xff, a, o); b += __shfl_xor_sync(0xff, b, o); }
            if (threadIdx.x == 0) { atomicAdd(&g_sumU2, a); atomicAdd(&g_sumM2, b); }
        }
    } else {
        float pw = decode_pw(pwp);
        int i = (blockIdx.x - 256) * 256 + threadIdx.x;
        float term = 0.f;
        {
            int lbl = g_labels[i];
            float wsum = (float)(g_hist[lbl] - 1);
            const float* s = soft + (size_t)i * C_SZ;
            float d = 0.f;
            #pragma unroll
            for (int c = 0; c < C_SZ; c++) d += s[c] * g_Ssum[c];
            wsum += pw * d;
            term = wsum * logf(g_rowsumE[i]);
        }
        #pragma unroll
        for (int o = 16; o; o >>= 1) term += __shfl_xor_sync(~0u, term, o);
        __shared__ float red[8];
        if ((threadIdx.x & 31) == 0) red[threadIdx.x >> 5] = term;
        __syncthreads();
        if (threadIdx.x < 8) {
            float v = red[threadIdx.x];
            #pragma unroll
            for (int o = 4; o; o >>= 1) v += __shfl_xor_sync(0xff, v, o);
            if (threadIdx.x == 0) atomicAdd(&g_accLog, v);
        }
    }
    // last-block finalization (deterministic; all contributions fenced before counter)
    if (threadIdx.x == 0) {
        __threadfence();
        unsigned t = atomicAdd(&g_done, 1u);
        if (t == 271u) {
            float pw = decode_pw(pwp);
            float P  = (g_sumM2 * S2INV - g_diagsum) * 10.0f;
            float SZ = (g_sumU2 * S2INV) * 10.0f;
            out[0] = (g_accLog - P - pw * SZ) / (float)B_SZ;
        }
    }
}

// ---------------- launch ----------------
extern "C" void kernel_launch(void* const* d_in, const int* in_sizes, int n_in,
                              void* d_out, int out_size) {
    const float* reps = (const float*)d_in[0];
    const float* soft = (const float*)d_in[1];
    const int*   lblp = (const int*)d_in[2];
    const void*  pwp  = d_in[3];
    float* out = (float*)d_out;
    (void)in_sizes; (void)n_in; (void)out_size;

    cudaFuncSetAttribute(k_fused, cudaFuncAttributeMaxDynamicSharedMemorySize, SM_TOT);

    k_init<<<16, 256>>>(lblp);
    k_norm<<<B_SZ, 256>>>(reps, soft);
    k_fused<<<NPAIR + NSMALL, 256, SM_TOT>>>(soft);
    k_tail<<<272, 256>>>(soft, pwp, out);
}

// round 17
// speedup vs baseline: 1.4152x; 1.0324x over previous
#include <cuda_runtime.h>
#include <cuda_bf16.h>
#include <cuda_fp16.h>
#include <cuda_fp8.h>
#include <cstdint>

#define B_SZ 4096
#define D_SZ 1024
#define C_SZ 32
// bf16 rn scaled by sqrt(10*log2(e)); U/M sums divided by S2 later
#define RNSCALE 3.7982825500f
#define S2INV   (1.0f/14.4269504089f)
// fp8 rn scaled by 16; epilogue: exp(10 z) = 2^(acc * QC), QC = 10*log2(e)/256
#define QSCALE  16.0f
#define QC      0.05635527503472513f

#define BM 128
#define BN 128
#define TTOT (B_SZ/BM)    // 32
#define NPAIR (TTOT*(TTOT+1)/2)  // 528
#define KT_G 8            // k-chunks of 128 fp8
#define CHUNK 16384       // one (tile, kt) chunk: 128 rows x 128B, SW128 swizzled

// dynamic smem layout (3-stage ring for gemm path; small path reuses front)
#define SM_AB(s)  ((s) * 32768)          // A at +0 (16KB), B at +16384
#define SM_MB     98304                   // 3 mbarriers
#define SM_ROW    98368
#define SM_COL    98880
#define SM_TOT    99392

// small GEMM (U|M): RN^T [1024 x 4096] @ [soft | onehot] [4096 x 64]
#define KSPLIT 16
#define KCH (B_SZ/KSPLIT)   // 256
#define NSM 64
#define NSMALL (8 * KSPLIT) // 128 blocks

// ---------------- device scratch ----------------
__device__ __align__(128) __nv_bfloat16 g_rn[B_SZ * D_SZ];   // bf16, scale RNSCALE
__device__ __align__(128) uint8_t       g_rq[B_SZ * D_SZ];   // e4m3, (tile,kt)-chunk SW128 layout
__device__ float g_rowsumE[B_SZ];
__device__ float g_part[KSPLIT * 8 * 128 * NSM];   // split-k partials (4MB)
__device__ float g_Ssum[C_SZ];
__device__ int   g_hist[C_SZ];
__device__ int   g_labels[B_SZ];
__device__ float g_diagsum;
__device__ float g_accLog;
__device__ float g_sumU2;
__device__ float g_sumM2;
__device__ unsigned g_done;

// ---------------- helpers ----------------
__device__ __forceinline__ float decode_pw(const void* p) {
    int v0 = ((const int*)p)[0];
    if (v0 > 0 && v0 < (1 << 26)) return (float)v0;
    float f = __int_as_float(v0);
    if (f > 0.0f && f < 1e8f) return f;
    return 0.0f;
}
__device__ __forceinline__ unsigned smem_u32(const void* p) {
    return (unsigned)__cvta_generic_to_shared(p);
}
__device__ __forceinline__ float ex2f(float x) {
    float y; asm("ex2.approx.f32 %0, %1;" : "=f"(y) : "f"(x)); return y;
}
__device__ __forceinline__ void mbar_init(uint32_t a, uint32_t cnt) {
    asm volatile("mbarrier.init.shared.b64 [%0], %1;" :: "r"(a), "r"(cnt) : "memory");
}
__device__ __forceinline__ void mbar_expect_tx(uint32_t a, uint32_t bytes) {
    asm volatile("mbarrier.arrive.expect_tx.shared.b64 _, [%0], %1;" :: "r"(a), "r"(bytes) : "memory");
}
__device__ __forceinline__ void mbar_wait(uint32_t a, uint32_t parity) {
    asm volatile(
        "{\n\t.reg .pred P;\n\t"
        "WL_%=:\n\t"
        "mbarrier.try_wait.parity.acquire.cta.shared::cta.b64 P, [%0], %1, 0x989680;\n\t"
        "@P bra.uni WD_%=;\n\t"
        "bra.uni WL_%=;\n\t"
        "WD_%=:\n\t}"
        :: "r"(a), "r"(parity) : "memory");
}
__device__ __forceinline__ void bulk_g2s(uint32_t dst, const void* src, uint32_t bytes, uint32_t mbar) {
    asm volatile("cp.async.bulk.shared::cluster.global.mbarrier::complete_tx::bytes [%0], [%1], %2, [%3];"
                 :: "r"(dst), "l"(src), "r"(bytes), "r"(mbar) : "memory");
}
__device__ __forceinline__ void ldm_x4(unsigned addr, unsigned &r0, unsigned &r1, unsigned &r2, unsigned &r3) {
    asm volatile("ldmatrix.sync.aligned.m8n8.x4.shared.b16 {%0,%1,%2,%3}, [%4];"
                 : "=r"(r0), "=r"(r1), "=r"(r2), "=r"(r3) : "r"(addr));
}
__device__ __forceinline__ void ldm_x4_t(unsigned addr, unsigned &r0, unsigned &r1, unsigned &r2, unsigned &r3) {
    asm volatile("ldmatrix.sync.aligned.m8n8.x4.trans.shared.b16 {%0,%1,%2,%3}, [%4];"
                 : "=r"(r0), "=r"(r1), "=r"(r2), "=r"(r3) : "r"(addr));
}
__device__ __forceinline__ void ldm_x2_t(unsigned addr, unsigned &r0, unsigned &r1) {
    asm volatile("ldmatrix.sync.aligned.m8n8.x2.trans.shared.b16 {%0,%1}, [%2];"
                 : "=r"(r0), "=r"(r1) : "r"(addr));
}
__device__ __forceinline__ void mma16816(float &c0, float &c1, float &c2, float &c3,
                                         unsigned a0, unsigned a1, unsigned a2, unsigned a3,
                                         unsigned b0, unsigned b1) {
    asm volatile("mma.sync.aligned.m16n8k16.row.col.f32.bf16.bf16.f32 "
                 "{%0,%1,%2,%3},{%4,%5,%6,%7},{%8,%9},{%0,%1,%2,%3};"
                 : "+f"(c0), "+f"(c1), "+f"(c2), "+f"(c3)
                 : "r"(a0), "r"(a1), "r"(a2), "r"(a3), "r"(b0), "r"(b1));
}
// fp8 mma with f16 accumulator
__device__ __forceinline__ void mma16832h(unsigned &c0, unsigned &c1,
                                          unsigned a0, unsigned a1, unsigned a2, unsigned a3,
                                          unsigned b0, unsigned b1) {
    asm volatile("mma.sync.aligned.m16n8k32.row.col.f16.e4m3.e4m3.f16 "
                 "{%0,%1},{%2,%3,%4,%5},{%6,%7},{%0,%1};"
                 : "+r"(c0), "+r"(c1)
                 : "r"(a0), "r"(a1), "r"(a2), "r"(a3), "r"(b0), "r"(b1));
}
__device__ __forceinline__ uint16_t fp8pair(float lo, float hi) {
    uint16_t r;
    asm("cvt.rn.satfinite.e4m3x2.f32 %0, %1, %2;" : "=h"(r) : "f"(hi), "f"(lo));
    return r;
}

// ---------------- kernels ----------------
// fused zero + label decode
__global__ void k_init(const int* __restrict__ p) {
    __shared__ int is64;
    if (threadIdx.x == 0) {
        int any = 0;
        #pragma unroll
        for (int i = 1; i < 128; i += 2) any |= p[i];
        is64 = (any == 0) ? 1 : 0;
    }
    __syncthreads();
    int s64 = is64;
    int i = blockIdx.x * 256 + threadIdx.x;
    if (i < B_SZ) {
        g_rowsumE[i] = 0.f;
        g_labels[i] = s64 ? p[2 * i] : p[i];
    }
    if (i < C_SZ) { g_Ssum[i] = 0.f; g_hist[i] = 0; }
    if (i == 0) { g_diagsum = 0.f; g_accLog = 0.f; g_sumU2 = 0.f; g_sumM2 = 0.f; g_done = 0u; }
}

// one-pass normalize: bf16 row-major + e4m3 (tile,kt)-chunk SW128 layout
__global__ __launch_bounds__(256) void k_norm(const float* __restrict__ reps, const float* __restrict__ soft) {
    int row = blockIdx.x;
    float4 v = ((const float4*)(reps + (size_t)row * D_SZ))[threadIdx.x];
    float ss = v.x * v.x + v.y * v.y + v.z * v.z + v.w * v.w;
    __shared__ float red[8];
    #pragma unroll
    for (int o = 16; o; o >>= 1) ss += __shfl_xor_sync(~0u, ss, o);
    if ((threadIdx.x & 31) == 0) red[threadIdx.x >> 5] = ss;
    __syncthreads();
    float sumsq = red[0] + red[1] + red[2] + red[3] + red[4] + red[5] + red[6] + red[7];
    float inv = 1.0f / fmaxf(sqrtf(sumsq), 1e-8f);
    float sc = inv * RNSCALE;
    __nv_bfloat162 p0 = __floats2bfloat162_rn(v.x * sc, v.y * sc);
    __nv_bfloat162 p1 = __floats2bfloat162_rn(v.z * sc, v.w * sc);
    uint2 pk; pk.x = *(uint32_t*)&p0; pk.y = *(uint32_t*)&p1;
    ((uint2*)(g_rn + (size_t)row * D_SZ))[threadIdx.x] = pk;
    float sq = inv * QSCALE;
    uint32_t q = (uint32_t)fp8pair(v.x * sq, v.y * sq)
               | ((uint32_t)fp8pair(v.z * sq, v.w * sq) << 16);
    {   // chunked + SW128-swizzled fp8 store (128B rows)
        int tile = row >> 7, lrow = row & 127;
        int ktc = threadIdx.x >> 5;               // col/128
        unsigned cb = (threadIdx.x & 31) * 4;     // byte within 128B chunk row
        unsigned quad = (cb >> 4) ^ ((unsigned)lrow & 7u);
        unsigned off = ((unsigned)lrow << 7) | (quad << 4) | (cb & 15);
        *(uint32_t*)(g_rq + ((size_t)(tile * KT_G + ktc) << 14) + off) = q;
    }
    if (threadIdx.x == 0) {
        atomicAdd(&g_diagsum, sumsq * inv * inv);
        atomicAdd(&g_hist[g_labels[row]], 1);
    }
    if (threadIdx.x < C_SZ) atomicAdd(&g_Ssum[threadIdx.x], soft[(size_t)row * C_SZ + threadIdx.x]);
}

// swizzled smem address within a 128B-row chunk: (row, 16B-quad qi)
__device__ __forceinline__ unsigned swz_addr(unsigned base, int row, int qi) {
    unsigned q = ((unsigned)qi ^ ((unsigned)row & 7u)) & 7u;
    return base + ((unsigned)row << 7) + (q << 4);
}

// ---- gemm path (blocks [0, NPAIR)) ----
__device__ void gemm_path(uint8_t* smem, int bidx) {
    const unsigned sb = smem_u32(smem);
    float* rowbuf = (float*)(smem + SM_ROW);
    float* colbuf = (float*)(smem + SM_COL);

    int idx = bidx;
    int I = 0;
    while (idx >= (TTOT - I)) { idx -= (TTOT - I); ++I; }
    int J = I + idx;
    bool diag = (I == J);

    int tid = threadIdx.x;
    int wid = tid >> 5, lane = tid & 31;
    int wm = wid & 1, wn = wid >> 1;       // 2x4 warps, 64x32 warp tiles

    if (tid < BM) { rowbuf[tid] = 0.f; colbuf[tid] = 0.f; }

    const uint8_t* gA = g_rq + ((size_t)I * KT_G << 14);
    const uint8_t* gB = g_rq + ((size_t)J * KT_G << 14);

    if (tid == 0) {
        #pragma unroll
        for (int s = 0; s < 3; s++) mbar_init(sb + SM_MB + s * 8, 1);
    }
    __syncthreads();
    if (tid == 0) {
        #pragma unroll
        for (int p = 0; p < 2; p++) {
            unsigned mb = sb + SM_MB + p * 8;
            mbar_expect_tx(mb, 2 * CHUNK);
            bulk_g2s(sb + SM_AB(p),         gA + p * CHUNK, CHUNK, mb);
            bulk_g2s(sb + SM_AB(p) + CHUNK, gB + p * CHUNK, CHUNK, mb);
        }
    }

    unsigned acc[4][4][2];
    #pragma unroll
    for (int a = 0; a < 4; a++)
        #pragma unroll
        for (int b = 0; b < 4; b++) { acc[a][b][0] = 0u; acc[a][b][1] = 0u; }

    const int arow0 = wm * 64 + (lane & 15);
    const int aq0   = lane >> 4;
    const int brow0 = wn * 32 + ((lane >> 4) << 3) + (lane & 7);
    const int bq0   = (lane >> 3) & 1;

    int st = 0, ph = 0;        // consumer stage cursor
    int pst = 2;               // producer stage cursor (fills kt+2)
    for (int kt = 0; kt < KT_G; ++kt) {
        if (kt) __syncthreads();            // all warps done reading the stage being refilled
        if (tid == 0 && kt + 2 < KT_G) {
            unsigned mb = sb + SM_MB + pst * 8;
            mbar_expect_tx(mb, 2 * CHUNK);
            bulk_g2s(sb + SM_AB(pst),         gA + (kt + 2) * CHUNK, CHUNK, mb);
            bulk_g2s(sb + SM_AB(pst) + CHUNK, gB + (kt + 2) * CHUNK, CHUNK, mb);
        }
        if (++pst == 3) pst = 0;
        mbar_wait(sb + SM_MB + st * 8, ph);
        unsigned aBase = sb + SM_AB(st);
        unsigned bBase = aBase + CHUNK;

        unsigned fa[2][4][4], fb[2][4][2];
        #pragma unroll
        for (int mi = 0; mi < 4; mi++)
            ldm_x4(swz_addr(aBase, arow0 + mi * 16, aq0),
                   fa[0][mi][0], fa[0][mi][1], fa[0][mi][2], fa[0][mi][3]);
        #pragma unroll
        for (int nj = 0; nj < 2; nj++)
            ldm_x4(swz_addr(bBase, brow0 + nj * 16, bq0),
                   fb[0][2 * nj][0], fb[0][2 * nj][1], fb[0][2 * nj + 1][0], fb[0][2 * nj + 1][1]);
        #pragma unroll
        for (int s = 0; s < 4; s++) {
            int cur = s & 1, nxt = cur ^ 1;
            if (s < 3) {
                #pragma unroll
                for (int mi = 0; mi < 4; mi++)
                    ldm_x4(swz_addr(aBase, arow0 + mi * 16, (s + 1) * 2 + aq0),
                           fa[nxt][mi][0], fa[nxt][mi][1], fa[nxt][mi][2], fa[nxt][mi][3]);
                #pragma unroll
                for (int nj = 0; nj < 2; nj++)
                    ldm_x4(swz_addr(bBase, brow0 + nj * 16, (s + 1) * 2 + bq0),
                           fb[nxt][2 * nj][0], fb[nxt][2 * nj][1],
                           fb[nxt][2 * nj + 1][0], fb[nxt][2 * nj + 1][1]);
            }
            #pragma unroll
            for (int mi = 0; mi < 4; mi++)
                #pragma unroll
                for (int ni = 0; ni < 4; ni++)
                    mma16832h(acc[mi][ni][0], acc[mi][ni][1],
                              fa[cur][mi][0], fa[cur][mi][1], fa[cur][mi][2], fa[cur][mi][3],
                              fb[cur][ni][0], fb[cur][ni][1]);
        }
        if (++st == 3) { st = 0; ph ^= 1; }
    }

    // epilogue: e = 2^(acc*QC); row sums (I) and col sums (J)
    int g = lane >> 2, t = lane & 3;
    int rbase = wm * 64, cbase = wn * 32;
    float colp[4][2];
    #pragma unroll
    for (int ni = 0; ni < 4; ni++) { colp[ni][0] = 0.f; colp[ni][1] = 0.f; }

    #pragma unroll
    for (int mi = 0; mi < 4; mi++) {
        float r0 = 0.f, r1 = 0.f;
        #pragma unroll
        for (int ni = 0; ni < 4; ni++) {
            float2 f0 = __half22float2(*(__half2*)&acc[mi][ni][0]);
            float2 f1 = __half22float2(*(__half2*)&acc[mi][ni][1]);
            float e0 = ex2f(f0.x * QC);
            float e1 = ex2f(f0.y * QC);
            float e2 = ex2f(f1.x * QC);
            float e3 = ex2f(f1.y * QC);
            if (diag) {
                int r = rbase + mi * 16 + g, c = cbase + ni * 8 + t * 2;
                if (r == c)     e0 = 0.f;
                if (r == c + 1) e1 = 0.f;
                if (r + 8 == c)     e2 = 0.f;
                if (r + 8 == c + 1) e3 = 0.f;
            }
            r0 += e0 + e1; r1 += e2 + e3;
            colp[ni][0] += e0 + e2; colp[ni][1] += e1 + e3;
        }
        r0 += __shfl_xor_sync(~0u, r0, 1); r0 += __shfl_xor_sync(~0u, r0, 2);
        r1 += __shfl_xor_sync(~0u, r1, 1); r1 += __shfl_xor_sync(~0u, r1, 2);
        if (t == 0) {
            atomicAdd(&rowbuf[rbase + mi * 16 + g],     r0);
            atomicAdd(&rowbuf[rbase + mi * 16 + g + 8], r1);
        }
    }
    if (!diag) {
        #pragma unroll
        for (int ni = 0; ni < 4; ni++) {
            #pragma unroll
            for (int p = 0; p < 2; p++) {
                float v = colp[ni][p];
                v += __shfl_xor_sync(~0u, v, 4);
                v += __shfl_xor_sync(~0u, v, 8);
                v += __shfl_xor_sync(~0u, v, 16);
                if (lane < 4) atomicAdd(&colbuf[cbase + ni * 8 + lane * 2 + p], v);
            }
        }
    }
    __syncthreads();
    if (tid < BM) {
        atomicAdd(&g_rowsumE[I * BM + tid], rowbuf[tid]);
        if (!diag) atomicAdd(&g_rowsumE[J * BN + tid], colbuf[tid]);
    }
}

// ---- small path (blocks [NPAIR, NPAIR+NSMALL)): [U|M] = RN^T @ [soft|onehot] ----
__device__ void small_path(uint8_t* smem, const float* __restrict__ soft, int sidx) {
    __nv_bfloat16 (*rn_s)[136] = (__nv_bfloat16(*)[136])(smem);          // 32x136 bf16 = 8704B
    __nv_bfloat16 (*sn_s)[72]  = (__nv_bfloat16(*)[72])(smem + 8704);    // 32x72  bf16 = 4608B

    int mtile = sidx & 7;       // 0..7
    int split = sidx >> 3;      // 0..KSPLIT-1
    int dbase = mtile * 128;
    int tid = threadIdx.x, lane = tid & 31, wid = tid >> 5;
    int wd = wid & 3, wn = wid >> 2;

    float acc[2][4][4];
    #pragma unroll
    for (int a = 0; a < 2; a++)
        #pragma unroll
        for (int b = 0; b < 4; b++)
            #pragma unroll
            for (int c = 0; c < 4; c++) acc[a][b][c] = 0.f;

    for (int ks = 0; ks < KCH / 32; ks++) {
        int i0 = split * KCH + ks * 32;
        #pragma unroll
        for (int j = 0; j < 2; j++) {
            int idx = tid + 256 * j;
            int row = idx >> 4, seg = idx & 15;
            *(uint4*)&rn_s[row][seg * 8] =
                *(const uint4*)(g_rn + (size_t)(i0 + row) * D_SZ + dbase + seg * 8);
        }
        {
            int i = tid >> 3, q = tid & 7;
            float4 sv = *(const float4*)(soft + (size_t)(i0 + i) * C_SZ + q * 4);
            __nv_bfloat162 p0 = __floats2bfloat162_rn(sv.x, sv.y);
            __nv_bfloat162 p1 = __floats2bfloat162_rn(sv.z, sv.w);
            uint2 pk; pk.x = *(uint32_t*)&p0; pk.y = *(uint32_t*)&p1;
            *(uint2*)&sn_s[i][q * 4] = pk;
            int lbl = g_labels[i0 + i];
            int n0 = q * 4;
            #pragma unroll
            for (int k = 0; k < 4; k++)
                sn_s[i][32 + n0 + k] = __float2bfloat16((lbl == n0 + k) ? 1.0f : 0.0f);
        }
        __syncthreads();

        unsigned a[2][2][4];
        #pragma unroll
        for (int mi = 0; mi < 2; mi++)
            #pragma unroll
            for (int kg = 0; kg < 2; kg++) {
                int krow = kg * 16 + (lane & 7) + ((lane >> 4) << 3);
                int mcol = wd * 32 + mi * 16 + ((lane >> 3) & 1) * 8;
                ldm_x4_t(smem_u32(&rn_s[krow][mcol]),
                         a[mi][kg][0], a[mi][kg][1], a[mi][kg][2], a[mi][kg][3]);
            }
        unsigned b[4][2][2];
        #pragma unroll
        for (int ni = 0; ni < 4; ni++)
            #pragma unroll
            for (int kg = 0; kg < 2; kg++) {
                int krow = kg * 16 + (lane & 15);
                ldm_x2_t(smem_u32(&sn_s[krow][wn * 32 + ni * 8]),
                         b[ni][kg][0], b[ni][kg][1]);
            }
        #pragma unroll
        for (int kg = 0; kg < 2; kg++)
            #pragma unroll
            for (int mi = 0; mi < 2; mi++)
                #pragma unroll
                for (int ni = 0; ni < 4; ni++)
                    mma16816(acc[mi][ni][0], acc[mi][ni][1], acc[mi][ni][2], acc[mi][ni][3],
                             a[mi][kg][0], a[mi][kg][1], a[mi][kg][2], a[mi][kg][3],
                             b[ni][kg][0], b[ni][kg][1]);
        __syncthreads();
    }

    #pragma unroll
    for (int mi = 0; mi < 2; mi++)
        #pragma unroll
        for (int ni = 0; ni < 4; ni++)
            #pragma unroll
            for (int r = 0; r < 4; r++) {
                int row = (lane >> 2) + (r >> 1) * 8;
                int col = (lane & 3) * 2 + (r & 1);
                int dl = wd * 32 + mi * 16 + row;
                int n  = wn * 32 + ni * 8 + col;
                g_part[((size_t)(split * 8 + mtile) * 128 + dl) * NSM + n] = acc[mi][ni][r];
            }
}

// fused heterogeneous kernel
__global__ __launch_bounds__(256, 2) void k_fused(const float* __restrict__ soft) {
    extern __shared__ __align__(128) uint8_t smem[];
    if (blockIdx.x < NPAIR) gemm_path(smem, blockIdx.x);
    else                    small_path(smem, soft, blockIdx.x - NPAIR);
}

// fused tail: blocks [0,256) reduce split-k partials; [256,272) row terms; last block writes out
__global__ void k_tail(const float* __restrict__ soft, const void* pwp, float* out) {
    if (blockIdx.x < 256) {
        int idx = blockIdx.x * 256 + threadIdx.x;
        float su = 0.f, sm = 0.f;
        {
            int d = idx >> 6, n = idx & 63;
            int mt = d >> 7, dl = d & 127;
            float s = 0.f;
            #pragma unroll
            for (int sp = 0; sp < KSPLIT; sp++)
                s += g_part[((size_t)(sp * 8 + mt) * 128 + dl) * NSM + n];
            if (n < C_SZ) su = s * s; else sm = s * s;
        }
        #pragma unroll
        for (int o = 16; o; o >>= 1) { su += __shfl_xor_sync(~0u, su, o); sm += __shfl_xor_sync(~0u, sm, o); }
        __shared__ float rs[8], rm[8];
        if ((threadIdx.x & 31) == 0) { rs[threadIdx.x >> 5] = su; rm[threadIdx.x >> 5] = sm; }
        __syncthreads();
        if (threadIdx.x < 8) {
            float a = rs[threadIdx.x], b = rm[threadIdx.x];
            #pragma unroll
            for (int o = 4; o; o >>= 1) { a += __shfl_xor_sync(0xff, a, o); b += __shfl_xor_sync(0xff, b, o); }
            if (threadIdx.x == 0) { atomicAdd(&g_sumU2, a); atomicAdd(&g_sumM2, b); }
        }
    } else {
        float pw = decode_pw(pwp);
        int i = (blockIdx.x - 256) * 256 + threadIdx.x;
        float term = 0.f;
        {
            int lbl = g_labels[i];
            float wsum = (float)(g_hist[lbl] - 1);
            const float* s = soft + (size_t)i * C_SZ;
            float d = 0.f;
            #pragma unroll
            for (int c = 0; c < C_SZ; c++) d += s[c] * g_Ssum[c];
            wsum += pw * d;
            term = wsum * logf(g_rowsumE[i]);
        }
        #pragma unroll
        for (int o = 16; o; o >>= 1) term += __shfl_xor_sync(~0u, term, o);
        __shared__ float red[8];
        if ((threadIdx.x & 31) == 0) red[threadIdx.x >> 5] = term;
        __syncthreads();
        if (threadIdx.x < 8) {
            float v = red[threadIdx.x];
            #pragma unroll
            for (int o = 4; o; o >>= 1) v += __shfl_xor_sync(0xff, v, o);
            if (threadIdx.x == 0) atomicAdd(&g_accLog, v);
        }
    }
    // last-block finalization (deterministic; all contributions fenced before counter)
    if (threadIdx.x == 0) {
        __threadfence();
        unsigned t = atomicAdd(&g_done, 1u);
        if (t == 271u) {
            float pw = decode_pw(pwp);
            float P  = (g_sumM2 * S2INV - g_diagsum) * 10.0f;
            float SZ = (g_sumU2 * S2INV) * 10.0f;
            out[0] = (g_accLog - P - pw * SZ) / (float)B_SZ;
        }
    }
}

// ---------------- launch ----------------
extern "C" void kernel_launch(void* const* d_in, const int* in_sizes, int n_in,
                              void* d_out, int out_size) {
    const float* reps = (const float*)d_in[0];
    const float* soft = (const float*)d_in[1];
    const int*   lblp = (const int*)d_in[2];
    const void*  pwp  = d_in[3];
    float* out = (float*)d_out;
    (void)in_sizes; (void)n_in; (void)out_size;

    cudaFuncSetAttribute(k_fused, cudaFuncAttributeMaxDynamicSharedMemorySize, SM_TOT);

    k_init<<<16, 256>>>(lblp);
    k_norm<<<B_SZ, 256>>>(reps, soft);
    k_fused<<<NPAIR + NSMALL, 256, SM_TOT>>>(soft);
    k_tail<<<272, 256>>>(soft, pwp, out);
}